// round 2
// baseline (speedup 1.0000x reference)
#include <cuda_runtime.h>

// ---------------------------------------------------------------------------
// GCN: h0 = relu(Â x W0 + b0); h1 = relu(Â h0 W1 + b1);
//      g = segment_sum(h1, graph); logits = relu(g Wm1 + bm1) Wm2 + bm2
// Â = D^-1/2 (A+I) D^-1/2. Self-loop folded into GEMM epilogue.
// ---------------------------------------------------------------------------

#define MAXN 100000
#define MAXE 1600000
#define MAXG 1000

__device__ float d_dinv[MAXN];          // deg, then rsqrt(deg)
__device__ float d_m0  [MAXN * 64];     // x @ W0
__device__ float d_agg0[MAXN * 64];     // aggregated layer-0
__device__ float d_m1  [MAXN * 32];     // h0 @ W1
__device__ float d_agg1[MAXN * 32];     // aggregated layer-1
__device__ float d_g   [MAXG * 32];     // pooled per-graph

__device__ __forceinline__ void red_add_v4(float* addr, float4 v) {
    asm volatile("red.global.add.v4.f32 [%0], {%1, %2, %3, %4};"
                 :: "l"(addr), "f"(v.x), "f"(v.y), "f"(v.z), "f"(v.w)
                 : "memory");
}

// ---------------- degree / norm ----------------
__global__ void k_deg_init(int N) {
    int i = blockIdx.x * blockDim.x + threadIdx.x;
    if (i < N) d_dinv[i] = 1.0f;  // self-loop weight
}

__global__ void k_deg_accum(const int* __restrict__ dst,
                            const float* __restrict__ w, int E) {
    int e = blockIdx.x * blockDim.x + threadIdx.x;
    if (e < E) atomicAdd(&d_dinv[dst[e]], w[e]);
}

__global__ void k_deg_finish(int N) {
    int i = blockIdx.x * blockDim.x + threadIdx.x;
    if (i < N) {
        float d = d_dinv[i];
        d_dinv[i] = d > 0.f ? rsqrtf(fmaxf(d, 1e-12f)) : 0.f;
    }
}

// ---------------- GEMM0: m0 = x @ W0 ; agg0 = m0*dinv^2 -------------------
// 64 rows/block, 256 threads, thread tile 4x4 over [64 x 64].
__global__ __launch_bounds__(256) void k_gemm0(const float* __restrict__ x,
                                               const float* __restrict__ W,
                                               int N) {
    __shared__ float Xs[64][129];
    int tid  = threadIdx.x;
    int row0 = blockIdx.x * 64;

    // stage 64 rows x 128 cols of x
    const float4* x4 = (const float4*)x;
#pragma unroll
    for (int i = 0; i < 8; i++) {
        int v  = tid + 256 * i;       // float4 index within tile
        int r  = v >> 5;
        int c4 = v & 31;
        int row = row0 + r;
        float4 val = (row < N) ? __ldg(x4 + row * 32 + c4)
                               : make_float4(0.f, 0.f, 0.f, 0.f);
        Xs[r][c4 * 4 + 0] = val.x;
        Xs[r][c4 * 4 + 1] = val.y;
        Xs[r][c4 * 4 + 2] = val.z;
        Xs[r][c4 * 4 + 3] = val.w;
    }
    __syncthreads();

    int ttx = tid & 15;   // col group: cols 4*ttx..
    int tty = tid >> 4;   // row group: rows 4*tty..
    float acc[4][4];
#pragma unroll
    for (int i = 0; i < 4; i++)
#pragma unroll
        for (int j = 0; j < 4; j++) acc[i][j] = 0.f;

    const float4* W4 = (const float4*)W;
#pragma unroll 4
    for (int k = 0; k < 128; k++) {
        float4 b = __ldg(W4 + k * 16 + ttx);
        float a0 = Xs[tty * 4 + 0][k];
        float a1 = Xs[tty * 4 + 1][k];
        float a2 = Xs[tty * 4 + 2][k];
        float a3 = Xs[tty * 4 + 3][k];
        acc[0][0] += a0 * b.x; acc[0][1] += a0 * b.y; acc[0][2] += a0 * b.z; acc[0][3] += a0 * b.w;
        acc[1][0] += a1 * b.x; acc[1][1] += a1 * b.y; acc[1][2] += a1 * b.z; acc[1][3] += a1 * b.w;
        acc[2][0] += a2 * b.x; acc[2][1] += a2 * b.y; acc[2][2] += a2 * b.z; acc[2][3] += a2 * b.w;
        acc[3][0] += a3 * b.x; acc[3][1] += a3 * b.y; acc[3][2] += a3 * b.z; acc[3][3] += a3 * b.w;
    }

#pragma unroll
    for (int i = 0; i < 4; i++) {
        int row = row0 + tty * 4 + i;
        if (row < N) {
            float di = d_dinv[row];
            float s  = di * di;
            float4 m = make_float4(acc[i][0], acc[i][1], acc[i][2], acc[i][3]);
            ((float4*)d_m0)[row * 16 + ttx] = m;
            ((float4*)d_agg0)[row * 16 + ttx] =
                make_float4(m.x * s, m.y * s, m.z * s, m.w * s);
        }
    }
}

// ---------------- scatter L0: agg0[dst] += m0[src]*nw ----------------------
__global__ void k_scatter0(const int* __restrict__ src,
                           const int* __restrict__ dst,
                           const float* __restrict__ w, int E) {
    int idx = blockIdx.x * blockDim.x + threadIdx.x;
    if (idx >= E * 16) return;
    int e = idx >> 4;
    int c = (idx & 15) << 2;
    int s = __ldg(src + e);
    int d = __ldg(dst + e);
    float nw = d_dinv[s] * d_dinv[d] * __ldg(w + e);
    float4 v = *(const float4*)(d_m0 + s * 64 + c);
    v.x *= nw; v.y *= nw; v.z *= nw; v.w *= nw;
    red_add_v4(d_agg0 + d * 64 + c, v);
}

// ---------------- GEMM1: m1 = relu(agg0+b0) @ W1 ; agg1 = m1*dinv^2 --------
// 128 rows/block, 256 threads, thread tile 4x4 over [128 x 32].
__global__ __launch_bounds__(256) void k_gemm1(const float* __restrict__ b0,
                                               const float* __restrict__ W,
                                               int N) {
    __shared__ float Xs[128][65];
    int tid  = threadIdx.x;
    int row0 = blockIdx.x * 128;

#pragma unroll
    for (int i = 0; i < 8; i++) {
        int v  = tid + 256 * i;      // float4 index
        int r  = v >> 4;
        int c4 = v & 15;
        int row = row0 + r;
        float4 val = (row < N) ? ((const float4*)d_agg0)[row * 16 + c4]
                               : make_float4(0.f, 0.f, 0.f, 0.f);
        float4 bb = __ldg((const float4*)b0 + c4);
        Xs[r][c4 * 4 + 0] = fmaxf(val.x + bb.x, 0.f);
        Xs[r][c4 * 4 + 1] = fmaxf(val.y + bb.y, 0.f);
        Xs[r][c4 * 4 + 2] = fmaxf(val.z + bb.z, 0.f);
        Xs[r][c4 * 4 + 3] = fmaxf(val.w + bb.w, 0.f);
    }
    __syncthreads();

    int ttx = tid & 7;    // col group: cols 4*ttx..
    int tty = tid >> 3;   // row group: rows 4*tty..
    float acc[4][4];
#pragma unroll
    for (int i = 0; i < 4; i++)
#pragma unroll
        for (int j = 0; j < 4; j++) acc[i][j] = 0.f;

    const float4* W4 = (const float4*)W;
#pragma unroll 4
    for (int k = 0; k < 64; k++) {
        float4 b = __ldg(W4 + k * 8 + ttx);
        float a0 = Xs[tty * 4 + 0][k];
        float a1 = Xs[tty * 4 + 1][k];
        float a2 = Xs[tty * 4 + 2][k];
        float a3 = Xs[tty * 4 + 3][k];
        acc[0][0] += a0 * b.x; acc[0][1] += a0 * b.y; acc[0][2] += a0 * b.z; acc[0][3] += a0 * b.w;
        acc[1][0] += a1 * b.x; acc[1][1] += a1 * b.y; acc[1][2] += a1 * b.z; acc[1][3] += a1 * b.w;
        acc[2][0] += a2 * b.x; acc[2][1] += a2 * b.y; acc[2][2] += a2 * b.z; acc[2][3] += a2 * b.w;
        acc[3][0] += a3 * b.x; acc[3][1] += a3 * b.y; acc[3][2] += a3 * b.z; acc[3][3] += a3 * b.w;
    }

#pragma unroll
    for (int i = 0; i < 4; i++) {
        int row = row0 + tty * 4 + i;
        if (row < N) {
            float di = d_dinv[row];
            float s  = di * di;
            float4 m = make_float4(acc[i][0], acc[i][1], acc[i][2], acc[i][3]);
            ((float4*)d_m1)[row * 8 + ttx] = m;
            ((float4*)d_agg1)[row * 8 + ttx] =
                make_float4(m.x * s, m.y * s, m.z * s, m.w * s);
        }
    }
}

// ---------------- scatter L1 ----------------------------------------------
__global__ void k_scatter1(const int* __restrict__ src,
                           const int* __restrict__ dst,
                           const float* __restrict__ w, int E) {
    int idx = blockIdx.x * blockDim.x + threadIdx.x;
    if (idx >= E * 8) return;
    int e = idx >> 3;
    int c = (idx & 7) << 2;
    int s = __ldg(src + e);
    int d = __ldg(dst + e);
    float nw = d_dinv[s] * d_dinv[d] * __ldg(w + e);
    float4 v = *(const float4*)(d_m1 + s * 32 + c);
    v.x *= nw; v.y *= nw; v.z *= nw; v.w *= nw;
    red_add_v4(d_agg1 + d * 32 + c, v);
}

// ---------------- pooling --------------------------------------------------
__global__ void k_gzero(int NG) {
    int i = blockIdx.x * blockDim.x + threadIdx.x;
    if (i < NG * 32) d_g[i] = 0.f;
}

// one warp handles 32 consecutive nodes for one 4-col chunk; node_graph_index
// is sorted, so most warps are graph-uniform -> single red per warp.
__global__ void k_pool(const int* __restrict__ ngi,
                       const float* __restrict__ b1, int N) {
    int gt     = blockIdx.x * blockDim.x + threadIdx.x;
    int warpId = gt >> 5;
    int lane   = gt & 31;
    int chunk  = warpId & 7;
    int nodeBase = (warpId >> 3) << 5;
    int node   = nodeBase + lane;
    int c      = chunk << 2;

    float4 v = make_float4(0.f, 0.f, 0.f, 0.f);
    int gi = -1;
    if (node < N) {
        gi = __ldg(ngi + node);
        float4 a  = *(const float4*)(d_agg1 + node * 32 + c);
        float4 bb = __ldg((const float4*)b1 + chunk);
        v.x = fmaxf(a.x + bb.x, 0.f);
        v.y = fmaxf(a.y + bb.y, 0.f);
        v.z = fmaxf(a.z + bb.z, 0.f);
        v.w = fmaxf(a.w + bb.w, 0.f);
    }
    int gi0  = __shfl_sync(0xffffffffu, gi, 0);
    int gi31 = __shfl_sync(0xffffffffu, gi, 31);
    if (gi0 == gi31 && gi0 >= 0) {
#pragma unroll
        for (int off = 16; off; off >>= 1) {
            v.x += __shfl_xor_sync(0xffffffffu, v.x, off);
            v.y += __shfl_xor_sync(0xffffffffu, v.y, off);
            v.z += __shfl_xor_sync(0xffffffffu, v.z, off);
            v.w += __shfl_xor_sync(0xffffffffu, v.w, off);
        }
        if (lane == 0) red_add_v4(d_g + gi0 * 32 + c, v);
    } else if (gi >= 0) {
        red_add_v4(d_g + gi * 32 + c, v);
    }
}

// ---------------- MLP head -------------------------------------------------
__global__ __launch_bounds__(128) void k_mlp(const float* __restrict__ Wm1,
                                             const float* __restrict__ bm1,
                                             const float* __restrict__ Wm2,
                                             const float* __restrict__ bm2,
                                             float* __restrict__ out) {
    __shared__ float gs[32];
    __shared__ float hs[128];
    int gr = blockIdx.x;
    int t  = threadIdx.x;
    if (t < 32) gs[t] = d_g[gr * 32 + t];
    __syncthreads();
    float acc = __ldg(bm1 + t);
#pragma unroll
    for (int k = 0; k < 32; k++) acc += gs[k] * __ldg(Wm1 + k * 128 + t);
    hs[t] = fmaxf(acc, 0.f);
    __syncthreads();
    if (t < 2) {
        float a = __ldg(bm2 + t);
#pragma unroll 8
        for (int k = 0; k < 128; k++) a += hs[k] * __ldg(Wm2 + k * 2 + t);
        out[gr * 2 + t] = a;
    }
}

// ---------------------------------------------------------------------------
extern "C" void kernel_launch(void* const* d_in, const int* in_sizes, int n_in,
                              void* d_out, int out_size) {
    const float* x   = (const float*)d_in[0];
    const int*   ei  = (const int*)d_in[1];
    const float* ew  = (const float*)d_in[2];
    const int*   ngi = (const int*)d_in[3];
    const float* W0  = (const float*)d_in[4];
    const float* b0  = (const float*)d_in[5];
    const float* W1  = (const float*)d_in[6];
    const float* b1  = (const float*)d_in[7];
    const float* Wm1 = (const float*)d_in[8];
    const float* bm1 = (const float*)d_in[9];
    const float* Wm2 = (const float*)d_in[10];
    const float* bm2 = (const float*)d_in[11];
    float* out = (float*)d_out;

    int N  = in_sizes[0] / 128;
    int E  = in_sizes[2];
    int NG = out_size / 2;
    const int* src = ei;
    const int* dst = ei + E;

    k_deg_init  <<<(N + 255) / 256, 256>>>(N);
    k_deg_accum <<<(E + 255) / 256, 256>>>(dst, ew, E);
    k_deg_finish<<<(N + 255) / 256, 256>>>(N);

    k_gemm0   <<<(N + 63) / 64, 256>>>(x, W0, N);
    k_scatter0<<<(E * 16 + 255) / 256, 256>>>(src, dst, ew, E);

    k_gemm1   <<<(N + 127) / 128, 256>>>(b0, W1, N);
    k_scatter1<<<(E * 8 + 255) / 256, 256>>>(src, dst, ew, E);

    k_gzero<<<(NG * 32 + 255) / 256, 256>>>(NG);
    int warps = ((N + 31) / 32) * 8;
    k_pool <<<(warps * 32 + 255) / 256, 256>>>(ngi, b1, N);

    k_mlp<<<NG, 128>>>(Wm1, bm1, Wm2, bm2, out);
}

// round 4
// speedup vs baseline: 1.0290x; 1.0290x over previous
#include <cuda_runtime.h>

// ---------------------------------------------------------------------------
// GCN: h0 = relu(Â x W0 + b0); h1 = relu(Â h0 W1 + b1);
//      g = segment_sum(h1, graph); logits = relu(g Wm1 + bm1) Wm2 + bm2
// Â = D^-1/2 (A+I) D^-1/2. Self-loop folded into GEMM epilogue.
// GEMMs use packed fp32x2 FMA (FFMA2) with A staged transposed in shared.
// ---------------------------------------------------------------------------

#define MAXN 100000
#define MAXE 1600000
#define MAXG 1000

__device__ float d_dinv[MAXN];          // deg, then rsqrt(deg)
__device__ float d_nw  [MAXE];          // per-edge normalized weight
__device__ float d_m0  [MAXN * 64];     // x @ W0
__device__ float d_agg0[MAXN * 64];     // aggregated layer-0
__device__ float d_m1  [MAXN * 32];     // h0 @ W1
__device__ float d_agg1[MAXN * 32];     // aggregated layer-1
__device__ float d_g   [MAXG * 32];     // pooled per-graph

__device__ __forceinline__ void red_add_v4(float* addr, float4 v) {
    asm volatile("red.global.add.v4.f32 [%0], {%1, %2, %3, %4};"
                 :: "l"(addr), "f"(v.x), "f"(v.y), "f"(v.z), "f"(v.w)
                 : "memory");
}

#define FMA2(d, a, b) \
    asm("fma.rn.f32x2 %0, %1, %2, %0;" : "+l"(d) : "l"(a), "l"(b))

__device__ __forceinline__ float f2lo(unsigned long long v) {
    return __uint_as_float((unsigned)v);
}
__device__ __forceinline__ float f2hi(unsigned long long v) {
    return __uint_as_float((unsigned)(v >> 32));
}
__device__ __forceinline__ unsigned long long rep2(float f) {
    unsigned long long r;
    asm("mov.b64 %0, {%1, %1};" : "=l"(r) : "r"(__float_as_uint(f)));
    return r;
}

// ---------------- degree / norm ----------------
__global__ void k_deg_init(int N) {
    int i = blockIdx.x * blockDim.x + threadIdx.x;
    if (i < N) d_dinv[i] = 1.0f;  // self-loop weight
}

__global__ void k_deg_accum(const int* __restrict__ dst,
                            const float* __restrict__ w, int E) {
    int e = blockIdx.x * blockDim.x + threadIdx.x;
    if (e < E) atomicAdd(&d_dinv[dst[e]], w[e]);
}

__global__ void k_deg_finish(int N) {
    int i = blockIdx.x * blockDim.x + threadIdx.x;
    if (i < N) {
        float d = d_dinv[i];
        d_dinv[i] = d > 0.f ? rsqrtf(fmaxf(d, 1e-12f)) : 0.f;
    }
}

__global__ void k_norm(const int* __restrict__ src,
                       const int* __restrict__ dst,
                       const float* __restrict__ w, int E) {
    int e = blockIdx.x * blockDim.x + threadIdx.x;
    if (e < E)
        d_nw[e] = d_dinv[__ldg(src + e)] * d_dinv[__ldg(dst + e)] * __ldg(w + e);
}

// ---------------- GEMM0: m0 = x @ W0 ; agg0 = m0*dinv^2 -------------------
// Tile 128 rows x 64 cols, 256 threads, thread tile 8x4, FFMA2 row-pairs.
// A staged transposed (k-major) so row-pairs load as f32x2 directly.
__global__ __launch_bounds__(256) void k_gemm0(const float* __restrict__ x,
                                               const float* __restrict__ W,
                                               int N) {
    __shared__ float XsT[32][132];   // [k][row], stride 132 (16B aligned rows)
    int tid  = threadIdx.x;
    int row0 = blockIdx.x * 128;
    int ttx  = tid & 15;             // cols 4*ttx
    int tty  = tid >> 4;             // rows 8*tty
    unsigned abase = (unsigned)__cvta_generic_to_shared(XsT) + tty * 32;

    unsigned long long acc[4][4];
#pragma unroll
    for (int p = 0; p < 4; p++)
#pragma unroll
        for (int c = 0; c < 4; c++) acc[p][c] = 0ull;

    const float4* x4 = (const float4*)x;
    const float4* W4 = (const float4*)W;

    for (int kc = 0; kc < 4; kc++) {
#pragma unroll
        for (int i = 0; i < 4; i++) {
            int v  = tid + 256 * i;       // 1024 float4 = 128 rows x 8 c4
            int rl = v >> 3;
            int c4 = v & 7;
            int row = row0 + rl;
            float4 val = (row < N) ? __ldg(x4 + row * 32 + kc * 8 + c4)
                                   : make_float4(0.f, 0.f, 0.f, 0.f);
            XsT[c4 * 4 + 0][rl] = val.x;
            XsT[c4 * 4 + 1][rl] = val.y;
            XsT[c4 * 4 + 2][rl] = val.z;
            XsT[c4 * 4 + 3][rl] = val.w;
        }
        __syncthreads();

#pragma unroll 4
        for (int k = 0; k < 32; k++) {
            unsigned long long a0, a1, a2, a3;
            unsigned adr = abase + (unsigned)(k * 132 * 4);
            asm("ld.shared.v2.u64 {%0, %1}, [%2];" : "=l"(a0), "=l"(a1) : "r"(adr));
            asm("ld.shared.v2.u64 {%0, %1}, [%2];" : "=l"(a2), "=l"(a3) : "r"(adr + 16));
            float4 b = __ldg(W4 + (kc * 32 + k) * 16 + ttx);
            unsigned long long bx = rep2(b.x), by = rep2(b.y),
                               bz = rep2(b.z), bw = rep2(b.w);
            FMA2(acc[0][0], a0, bx); FMA2(acc[0][1], a0, by);
            FMA2(acc[0][2], a0, bz); FMA2(acc[0][3], a0, bw);
            FMA2(acc[1][0], a1, bx); FMA2(acc[1][1], a1, by);
            FMA2(acc[1][2], a1, bz); FMA2(acc[1][3], a1, bw);
            FMA2(acc[2][0], a2, bx); FMA2(acc[2][1], a2, by);
            FMA2(acc[2][2], a2, bz); FMA2(acc[2][3], a2, bw);
            FMA2(acc[3][0], a3, bx); FMA2(acc[3][1], a3, by);
            FMA2(acc[3][2], a3, bz); FMA2(acc[3][3], a3, bw);
        }
        __syncthreads();
    }

#pragma unroll
    for (int p = 0; p < 4; p++) {
        int r0 = row0 + tty * 8 + 2 * p;
        if (r0 < N) {
            float di = d_dinv[r0];
            float s  = di * di;
            float4 m = make_float4(f2lo(acc[p][0]), f2lo(acc[p][1]),
                                   f2lo(acc[p][2]), f2lo(acc[p][3]));
            ((float4*)d_m0)[r0 * 16 + ttx] = m;
            ((float4*)d_agg0)[r0 * 16 + ttx] =
                make_float4(m.x * s, m.y * s, m.z * s, m.w * s);
        }
        int r1 = r0 + 1;
        if (r1 < N) {
            float di = d_dinv[r1];
            float s  = di * di;
            float4 m = make_float4(f2hi(acc[p][0]), f2hi(acc[p][1]),
                                   f2hi(acc[p][2]), f2hi(acc[p][3]));
            ((float4*)d_m0)[r1 * 16 + ttx] = m;
            ((float4*)d_agg1 != 0 ? (float4*)d_agg0 : (float4*)d_agg0)[r1 * 16 + ttx] =
                make_float4(m.x * s, m.y * s, m.z * s, m.w * s);
        }
    }
}

// ---------------- scatter L0: agg0[dst] += m0[src]*nw ----------------------
__global__ void k_scatter0(const int* __restrict__ src,
                           const int* __restrict__ dst, int E) {
    int idx = blockIdx.x * blockDim.x + threadIdx.x;
    if (idx >= E * 16) return;
    int e = idx >> 4;
    int c = (idx & 15) << 2;
    int s = __ldg(src + e);
    int d = __ldg(dst + e);
    float nw = __ldg(d_nw + e);
    float4 v = *(const float4*)(d_m0 + s * 64 + c);
    v.x *= nw; v.y *= nw; v.z *= nw; v.w *= nw;
    red_add_v4(d_agg0 + d * 64 + c, v);
}

// ---------------- GEMM1: m1 = relu(agg0+b0) @ W1 ; agg1 = m1*dinv^2 --------
// Tile 256 rows x 32 cols, 256 threads, thread tile 8x4, FFMA2.
__global__ __launch_bounds__(256) void k_gemm1(const float* __restrict__ b0,
                                               const float* __restrict__ W,
                                               int N) {
    __shared__ float XsT[32][260];   // [k][row], 256 rows + pad (16B aligned)
    int tid  = threadIdx.x;
    int row0 = blockIdx.x * 256;
    int ttx  = tid & 7;              // cols 4*ttx
    int tty  = tid >> 3;             // rows 8*tty
    unsigned abase = (unsigned)__cvta_generic_to_shared(XsT) + tty * 32;

    unsigned long long acc[4][4];
#pragma unroll
    for (int p = 0; p < 4; p++)
#pragma unroll
        for (int c = 0; c < 4; c++) acc[p][c] = 0ull;

    const float4* A4  = (const float4*)d_agg0;
    const float4* W4  = (const float4*)W;
    const float4* bb4 = (const float4*)b0;

    for (int kc = 0; kc < 2; kc++) {
#pragma unroll
        for (int i = 0; i < 8; i++) {
            int v  = tid + 256 * i;       // 2048 float4 = 256 rows x 8 c4
            int rl = v >> 3;
            int c4 = v & 7;
            int row = row0 + rl;
            float4 val = (row < N) ? A4[row * 16 + kc * 8 + c4]
                                   : make_float4(0.f, 0.f, 0.f, 0.f);
            float4 bv = __ldg(bb4 + kc * 8 + c4);
            XsT[c4 * 4 + 0][rl] = fmaxf(val.x + bv.x, 0.f);
            XsT[c4 * 4 + 1][rl] = fmaxf(val.y + bv.y, 0.f);
            XsT[c4 * 4 + 2][rl] = fmaxf(val.z + bv.z, 0.f);
            XsT[c4 * 4 + 3][rl] = fmaxf(val.w + bv.w, 0.f);
        }
        __syncthreads();

#pragma unroll 4
        for (int k = 0; k < 32; k++) {
            unsigned long long a0, a1, a2, a3;
            unsigned adr = abase + (unsigned)(k * 260 * 4);
            asm("ld.shared.v2.u64 {%0, %1}, [%2];" : "=l"(a0), "=l"(a1) : "r"(adr));
            asm("ld.shared.v2.u64 {%0, %1}, [%2];" : "=l"(a2), "=l"(a3) : "r"(adr + 16));
            float4 b = __ldg(W4 + (kc * 32 + k) * 8 + ttx);
            unsigned long long bx = rep2(b.x), by = rep2(b.y),
                               bz = rep2(b.z), bw = rep2(b.w);
            FMA2(acc[0][0], a0, bx); FMA2(acc[0][1], a0, by);
            FMA2(acc[0][2], a0, bz); FMA2(acc[0][3], a0, bw);
            FMA2(acc[1][0], a1, bx); FMA2(acc[1][1], a1, by);
            FMA2(acc[1][2], a1, bz); FMA2(acc[1][3], a1, bw);
            FMA2(acc[2][0], a2, bx); FMA2(acc[2][1], a2, by);
            FMA2(acc[2][2], a2, bz); FMA2(acc[2][3], a2, bw);
            FMA2(acc[3][0], a3, bx); FMA2(acc[3][1], a3, by);
            FMA2(acc[3][2], a3, bz); FMA2(acc[3][3], a3, bw);
        }
        __syncthreads();
    }

#pragma unroll
    for (int p = 0; p < 4; p++) {
        int r0 = row0 + tty * 8 + 2 * p;
        if (r0 < N) {
            float di = d_dinv[r0];
            float s  = di * di;
            float4 m = make_float4(f2lo(acc[p][0]), f2lo(acc[p][1]),
                                   f2lo(acc[p][2]), f2lo(acc[p][3]));
            ((float4*)d_m1)[r0 * 8 + ttx] = m;
            ((float4*)d_agg1)[r0 * 8 + ttx] =
                make_float4(m.x * s, m.y * s, m.z * s, m.w * s);
        }
        int r1 = r0 + 1;
        if (r1 < N) {
            float di = d_dinv[r1];
            float s  = di * di;
            float4 m = make_float4(f2hi(acc[p][0]), f2hi(acc[p][1]),
                                   f2hi(acc[p][2]), f2hi(acc[p][3]));
            ((float4*)d_m1)[r1 * 8 + ttx] = m;
            ((float4*)d_agg1)[r1 * 8 + ttx] =
                make_float4(m.x * s, m.y * s, m.z * s, m.w * s);
        }
    }
}

// ---------------- scatter L1 ----------------------------------------------
__global__ void k_scatter1(const int* __restrict__ src,
                           const int* __restrict__ dst, int E) {
    int idx = blockIdx.x * blockDim.x + threadIdx.x;
    if (idx >= E * 8) return;
    int e = idx >> 3;
    int c = (idx & 7) << 2;
    int s = __ldg(src + e);
    int d = __ldg(dst + e);
    float nw = __ldg(d_nw + e);
    float4 v = *(const float4*)(d_m1 + s * 32 + c);
    v.x *= nw; v.y *= nw; v.z *= nw; v.w *= nw;
    red_add_v4(d_agg1 + d * 32 + c, v);
}

// ---------------- pooling --------------------------------------------------
__global__ void k_gzero(int NG) {
    int i = blockIdx.x * blockDim.x + threadIdx.x;
    if (i < NG * 32) d_g[i] = 0.f;
}

__global__ void k_pool(const int* __restrict__ ngi,
                       const float* __restrict__ b1, int N) {
    int gt     = blockIdx.x * blockDim.x + threadIdx.x;
    int warpId = gt >> 5;
    int lane   = gt & 31;
    int chunk  = warpId & 7;
    int nodeBase = (warpId >> 3) << 5;
    int node   = nodeBase + lane;
    int c      = chunk << 2;

    float4 v = make_float4(0.f, 0.f, 0.f, 0.f);
    int gi = -1;
    if (node < N) {
        gi = __ldg(ngi + node);
        float4 a  = *(const float4*)(d_agg1 + node * 32 + c);
        float4 bb = __ldg((const float4*)b1 + chunk);
        v.x = fmaxf(a.x + bb.x, 0.f);
        v.y = fmaxf(a.y + bb.y, 0.f);
        v.z = fmaxf(a.z + bb.z, 0.f);
        v.w = fmaxf(a.w + bb.w, 0.f);
    }
    int gi0  = __shfl_sync(0xffffffffu, gi, 0);
    int gi31 = __shfl_sync(0xffffffffu, gi, 31);
    if (gi0 == gi31 && gi0 >= 0) {
#pragma unroll
        for (int off = 16; off; off >>= 1) {
            v.x += __shfl_xor_sync(0xffffffffu, v.x, off);
            v.y += __shfl_xor_sync(0xffffffffu, v.y, off);
            v.z += __shfl_xor_sync(0xffffffffu, v.z, off);
            v.w += __shfl_xor_sync(0xffffffffu, v.w, off);
        }
        if (lane == 0) red_add_v4(d_g + gi0 * 32 + c, v);
    } else if (gi >= 0) {
        red_add_v4(d_g + gi * 32 + c, v);
    }
}

// ---------------- MLP head -------------------------------------------------
__global__ __launch_bounds__(128) void k_mlp(const float* __restrict__ Wm1,
                                             const float* __restrict__ bm1,
                                             const float* __restrict__ Wm2,
                                             const float* __restrict__ bm2,
                                             float* __restrict__ out) {
    __shared__ float gs[32];
    __shared__ float hs[128];
    int gr = blockIdx.x;
    int t  = threadIdx.x;
    if (t < 32) gs[t] = d_g[gr * 32 + t];
    __syncthreads();
    float acc = __ldg(bm1 + t);
#pragma unroll
    for (int k = 0; k < 32; k++) acc += gs[k] * __ldg(Wm1 + k * 128 + t);
    hs[t] = fmaxf(acc, 0.f);
    __syncthreads();
    if (t < 2) {
        float a = __ldg(bm2 + t);
#pragma unroll 8
        for (int k = 0; k < 128; k++) a += hs[k] * __ldg(Wm2 + k * 2 + t);
        out[gr * 2 + t] = a;
    }
}

// ---------------------------------------------------------------------------
extern "C" void kernel_launch(void* const* d_in, const int* in_sizes, int n_in,
                              void* d_out, int out_size) {
    const float* x   = (const float*)d_in[0];
    const int*   ei  = (const int*)d_in[1];
    const float* ew  = (const float*)d_in[2];
    const int*   ngi = (const int*)d_in[3];
    const float* W0  = (const float*)d_in[4];
    const float* b0  = (const float*)d_in[5];
    const float* W1  = (const float*)d_in[6];
    const float* b1  = (const float*)d_in[7];
    const float* Wm1 = (const float*)d_in[8];
    const float* bm1 = (const float*)d_in[9];
    const float* Wm2 = (const float*)d_in[10];
    const float* bm2 = (const float*)d_in[11];
    float* out = (float*)d_out;

    int N  = in_sizes[0] / 128;
    int E  = in_sizes[2];
    int NG = out_size / 2;
    const int* src = ei;
    const int* dst = ei + E;

    k_deg_init  <<<(N + 255) / 256, 256>>>(N);
    k_deg_accum <<<(E + 255) / 256, 256>>>(dst, ew, E);
    k_deg_finish<<<(N + 255) / 256, 256>>>(N);
    k_norm      <<<(E + 255) / 256, 256>>>(src, dst, ew, E);

    k_gemm0   <<<(N + 127) / 128, 256>>>(x, W0, N);
    k_scatter0<<<(E * 16 + 255) / 256, 256>>>(src, dst, E);

    k_gemm1   <<<(N + 255) / 256, 256>>>(b0, W1, N);
    k_scatter1<<<(E * 8 + 255) / 256, 256>>>(src, dst, E);

    k_gzero<<<(NG * 32 + 255) / 256, 256>>>(NG);
    int warps = ((N + 31) / 32) * 8;
    k_pool <<<(warps * 32 + 255) / 256, 256>>>(ngi, b1, N);

    k_mlp<<<NG, 128>>>(Wm1, bm1, Wm2, bm2, out);
}

// round 6
// speedup vs baseline: 1.4413x; 1.4006x over previous
#include <cuda_runtime.h>

// ---------------------------------------------------------------------------
// GCN: h0 = relu(Â x W0 + b0); h1 = relu(Â h0 W1 + b1);
//      g = segment_sum(h1, graph); logits = relu(g Wm1 + bm1) Wm2 + bm2
// Â = D^-1/2 (A+I) D^-1/2.
// This round: CSR-by-dst built per call; aggregation is a GATHER (LDG) not a
// scatter (REDG). GEMM epilogue writes ms = (h@W)*dinv, so
// agg[d] = dinv[d] * (ms[d] + sum_in ms[src]*w)  -- no per-edge dinv gathers.
// ---------------------------------------------------------------------------

#define MAXN 100000
#define MAXE 1600000
#define MAXG 1000
#define MAXNB 128   // scan blocks: ceil(MAXN/1024)

__device__ int   d_cnt   [MAXN];
__device__ int   d_scan  [MAXN];
__device__ int   d_bsum  [MAXNB];
__device__ int   d_bscan [MAXNB];
__device__ int   d_rowptr[MAXN + 1];
__device__ int   d_cursor[MAXN];
__device__ int   d_csrc  [MAXE];      // CSR: src node per in-edge
__device__ float d_cw    [MAXE];      // CSR: raw edge weight
__device__ float d_dinv  [MAXN];
__device__ float d_ms0   [MAXN * 64]; // (x@W0)*dinv
__device__ float d_agg0  [MAXN * 64];
__device__ float d_ms1   [MAXN * 32]; // (h0@W1)*dinv
__device__ float d_agg1  [MAXN * 32];
__device__ float d_g     [MAXG * 32];

__device__ __forceinline__ void red_add_v4(float* addr, float4 v) {
    asm volatile("red.global.add.v4.f32 [%0], {%1, %2, %3, %4};"
                 :: "l"(addr), "f"(v.x), "f"(v.y), "f"(v.z), "f"(v.w)
                 : "memory");
}

#define FMA2(d, a, b) \
    asm("fma.rn.f32x2 %0, %1, %2, %0;" : "+l"(d) : "l"(a), "l"(b))

__device__ __forceinline__ float f2lo(unsigned long long v) {
    return __uint_as_float((unsigned)v);
}
__device__ __forceinline__ float f2hi(unsigned long long v) {
    return __uint_as_float((unsigned)(v >> 32));
}
__device__ __forceinline__ unsigned long long rep2(float f) {
    unsigned long long r;
    asm("mov.b64 %0, {%1, %1};" : "=l"(r) : "r"(__float_as_uint(f)));
    return r;
}

// ---------------- CSR build ----------------
__global__ void k_zero_cnt(int N) {
    int i = blockIdx.x * blockDim.x + threadIdx.x;
    if (i < N) d_cnt[i] = 0;
}

__global__ void k_hist(const int* __restrict__ dst, int E) {
    int e = blockIdx.x * blockDim.x + threadIdx.x;
    if (e < E) atomicAdd(&d_cnt[__ldg(dst + e)], 1);
}

__global__ __launch_bounds__(1024) void k_scanA(int N) {
    __shared__ int sh[1024];
    int i = blockIdx.x * 1024 + threadIdx.x;
    int v = (i < N) ? d_cnt[i] : 0;
    sh[threadIdx.x] = v;
    __syncthreads();
#pragma unroll
    for (int off = 1; off < 1024; off <<= 1) {
        int t = (threadIdx.x >= off) ? sh[threadIdx.x - off] : 0;
        __syncthreads();
        sh[threadIdx.x] += t;
        __syncthreads();
    }
    if (i < N) d_scan[i] = sh[threadIdx.x];
    if (threadIdx.x == 1023) d_bsum[blockIdx.x] = sh[1023];
}

__global__ __launch_bounds__(MAXNB) void k_scanB(int NB) {
    __shared__ int sh[MAXNB];
    int v = (threadIdx.x < NB) ? d_bsum[threadIdx.x] : 0;
    sh[threadIdx.x] = v;
    __syncthreads();
#pragma unroll
    for (int off = 1; off < MAXNB; off <<= 1) {
        int t = (threadIdx.x >= off) ? sh[threadIdx.x - off] : 0;
        __syncthreads();
        sh[threadIdx.x] += t;
        __syncthreads();
    }
    if (threadIdx.x < NB) d_bscan[threadIdx.x] = sh[threadIdx.x] - v;  // exclusive
}

__global__ __launch_bounds__(1024) void k_scanC(int N) {
    int i = blockIdx.x * 1024 + threadIdx.x;
    if (i < N) {
        int incl = d_scan[i] + d_bscan[blockIdx.x];
        d_rowptr[i + 1] = incl;
        d_cursor[i] = incl - d_cnt[i];
        if (i == 0) d_rowptr[0] = 0;
    }
}

__global__ void k_fill(const int* __restrict__ src,
                       const int* __restrict__ dst,
                       const float* __restrict__ w, int E) {
    int e = blockIdx.x * blockDim.x + threadIdx.x;
    if (e < E) {
        int d = __ldg(dst + e);
        int pos = atomicAdd(&d_cursor[d], 1);
        d_csrc[pos] = __ldg(src + e);
        d_cw[pos]   = __ldg(w + e);
    }
}

// deg[i] = 1 + sum of in-edge weights (CSR-resident, sequential reads)
__global__ void k_deg(int N) {
    int i = blockIdx.x * blockDim.x + threadIdx.x;
    if (i < N) {
        int s = d_rowptr[i], t = d_rowptr[i + 1];
        float acc = 1.0f;
        for (int j = s; j < t; j++) acc += __ldg(d_cw + j);
        d_dinv[i] = rsqrtf(fmaxf(acc, 1e-12f));
    }
}

// ---------------- GEMM0: ms0 = (x @ W0) * dinv ----------------------------
// Tile 128 rows x 64 cols, 256 threads, FFMA2 row-pairs.
__global__ __launch_bounds__(256) void k_gemm0(const float* __restrict__ x,
                                               const float* __restrict__ W,
                                               int N) {
    __shared__ float XsT[32][132];
    int tid  = threadIdx.x;
    int row0 = blockIdx.x * 128;
    int ttx  = tid & 15;
    int tty  = tid >> 4;
    unsigned abase = (unsigned)__cvta_generic_to_shared(XsT) + tty * 32;

    unsigned long long acc[4][4];
#pragma unroll
    for (int p = 0; p < 4; p++)
#pragma unroll
        for (int c = 0; c < 4; c++) acc[p][c] = 0ull;

    const float4* x4 = (const float4*)x;
    const float4* W4 = (const float4*)W;

    for (int kc = 0; kc < 4; kc++) {
#pragma unroll
        for (int i = 0; i < 4; i++) {
            int v  = tid + 256 * i;
            int rl = v >> 3;
            int c4 = v & 7;
            int row = row0 + rl;
            float4 val = (row < N) ? __ldg(x4 + row * 32 + kc * 8 + c4)
                                   : make_float4(0.f, 0.f, 0.f, 0.f);
            XsT[c4 * 4 + 0][rl] = val.x;
            XsT[c4 * 4 + 1][rl] = val.y;
            XsT[c4 * 4 + 2][rl] = val.z;
            XsT[c4 * 4 + 3][rl] = val.w;
        }
        __syncthreads();

#pragma unroll 4
        for (int k = 0; k < 32; k++) {
            unsigned long long a0, a1, a2, a3;
            unsigned adr = abase + (unsigned)(k * 132 * 4);
            asm("ld.shared.v2.u64 {%0, %1}, [%2];" : "=l"(a0), "=l"(a1) : "r"(adr));
            asm("ld.shared.v2.u64 {%0, %1}, [%2];" : "=l"(a2), "=l"(a3) : "r"(adr + 16));
            float4 b = __ldg(W4 + (kc * 32 + k) * 16 + ttx);
            unsigned long long bx = rep2(b.x), by = rep2(b.y),
                               bz = rep2(b.z), bw = rep2(b.w);
            FMA2(acc[0][0], a0, bx); FMA2(acc[0][1], a0, by);
            FMA2(acc[0][2], a0, bz); FMA2(acc[0][3], a0, bw);
            FMA2(acc[1][0], a1, bx); FMA2(acc[1][1], a1, by);
            FMA2(acc[1][2], a1, bz); FMA2(acc[1][3], a1, bw);
            FMA2(acc[2][0], a2, bx); FMA2(acc[2][1], a2, by);
            FMA2(acc[2][2], a2, bz); FMA2(acc[2][3], a2, bw);
            FMA2(acc[3][0], a3, bx); FMA2(acc[3][1], a3, by);
            FMA2(acc[3][2], a3, bz); FMA2(acc[3][3], a3, bw);
        }
        __syncthreads();
    }

#pragma unroll
    for (int p = 0; p < 4; p++) {
        int r0 = row0 + tty * 8 + 2 * p;
        if (r0 < N) {
            float di = d_dinv[r0];
            ((float4*)d_ms0)[r0 * 16 + ttx] =
                make_float4(f2lo(acc[p][0]) * di, f2lo(acc[p][1]) * di,
                            f2lo(acc[p][2]) * di, f2lo(acc[p][3]) * di);
        }
        int r1 = r0 + 1;
        if (r1 < N) {
            float di = d_dinv[r1];
            ((float4*)d_ms0)[r1 * 16 + ttx] =
                make_float4(f2hi(acc[p][0]) * di, f2hi(acc[p][1]) * di,
                            f2hi(acc[p][2]) * di, f2hi(acc[p][3]) * di);
        }
    }
}

// ---------------- gather L0: agg0[d] = dinv[d]*(ms0[d] + sum ms0[s]*w) -----
// 16 threads per node (64 cols = 16 x float4).
__global__ __launch_bounds__(256) void k_gather0(int N) {
    int gt   = blockIdx.x * blockDim.x + threadIdx.x;
    int node = gt >> 4;
    int lane = gt & 15;
    if (node >= N) return;
    int s0 = __ldg(d_rowptr + node);
    int s1 = __ldg(d_rowptr + node + 1);
    const float4* M = (const float4*)d_ms0;
    float4 acc = __ldg(M + node * 16 + lane);   // self term (ms0[node])
    int j = s0;
    for (; j + 1 < s1; j += 2) {
        int   a  = __ldg(d_csrc + j);
        int   b  = __ldg(d_csrc + j + 1);
        float wa = __ldg(d_cw + j);
        float wb = __ldg(d_cw + j + 1);
        float4 va = __ldg(M + a * 16 + lane);
        float4 vb = __ldg(M + b * 16 + lane);
        acc.x += va.x * wa + vb.x * wb;
        acc.y += va.y * wa + vb.y * wb;
        acc.z += va.z * wa + vb.z * wb;
        acc.w += va.w * wa + vb.w * wb;
    }
    if (j < s1) {
        int   a  = __ldg(d_csrc + j);
        float wa = __ldg(d_cw + j);
        float4 va = __ldg(M + a * 16 + lane);
        acc.x += va.x * wa; acc.y += va.y * wa;
        acc.z += va.z * wa; acc.w += va.w * wa;
    }
    float dn = __ldg(d_dinv + node);
    acc.x *= dn; acc.y *= dn; acc.z *= dn; acc.w *= dn;
    ((float4*)d_agg0)[node * 16 + lane] = acc;
}

// ---------------- GEMM1: ms1 = (relu(agg0+b0) @ W1) * dinv -----------------
__global__ __launch_bounds__(256) void k_gemm1(const float* __restrict__ b0,
                                               const float* __restrict__ W,
                                               int N) {
    __shared__ float XsT[32][260];
    int tid  = threadIdx.x;
    int row0 = blockIdx.x * 256;
    int ttx  = tid & 7;
    int tty  = tid >> 3;
    unsigned abase = (unsigned)__cvta_generic_to_shared(XsT) + tty * 32;

    unsigned long long acc[4][4];
#pragma unroll
    for (int p = 0; p < 4; p++)
#pragma unroll
        for (int c = 0; c < 4; c++) acc[p][c] = 0ull;

    const float4* A4  = (const float4*)d_agg0;
    const float4* W4  = (const float4*)W;
    const float4* bb4 = (const float4*)b0;

    for (int kc = 0; kc < 2; kc++) {
#pragma unroll
        for (int i = 0; i < 8; i++) {
            int v  = tid + 256 * i;
            int rl = v >> 3;
            int c4 = v & 7;
            int row = row0 + rl;
            float4 val = (row < N) ? A4[row * 16 + kc * 8 + c4]
                                   : make_float4(0.f, 0.f, 0.f, 0.f);
            float4 bv = __ldg(bb4 + kc * 8 + c4);
            XsT[c4 * 4 + 0][rl] = fmaxf(val.x + bv.x, 0.f);
            XsT[c4 * 4 + 1][rl] = fmaxf(val.y + bv.y, 0.f);
            XsT[c4 * 4 + 2][rl] = fmaxf(val.z + bv.z, 0.f);
            XsT[c4 * 4 + 3][rl] = fmaxf(val.w + bv.w, 0.f);
        }
        __syncthreads();

#pragma unroll 4
        for (int k = 0; k < 32; k++) {
            unsigned long long a0, a1, a2, a3;
            unsigned adr = abase + (unsigned)(k * 260 * 4);
            asm("ld.shared.v2.u64 {%0, %1}, [%2];" : "=l"(a0), "=l"(a1) : "r"(adr));
            asm("ld.shared.v2.u64 {%0, %1}, [%2];" : "=l"(a2), "=l"(a3) : "r"(adr + 16));
            float4 b = __ldg(W4 + (kc * 32 + k) * 8 + ttx);
            unsigned long long bx = rep2(b.x), by = rep2(b.y),
                               bz = rep2(b.z), bw = rep2(b.w);
            FMA2(acc[0][0], a0, bx); FMA2(acc[0][1], a0, by);
            FMA2(acc[0][2], a0, bz); FMA2(acc[0][3], a0, bw);
            FMA2(acc[1][0], a1, bx); FMA2(acc[1][1], a1, by);
            FMA2(acc[1][2], a1, bz); FMA2(acc[1][3], a1, bw);
            FMA2(acc[2][0], a2, bx); FMA2(acc[2][1], a2, by);
            FMA2(acc[2][2], a2, bz); FMA2(acc[2][3], a2, bw);
            FMA2(acc[3][0], a3, bx); FMA2(acc[3][1], a3, by);
            FMA2(acc[3][2], a3, bz); FMA2(acc[3][3], a3, bw);
        }
        __syncthreads();
    }

#pragma unroll
    for (int p = 0; p < 4; p++) {
        int r0 = row0 + tty * 8 + 2 * p;
        if (r0 < N) {
            float di = d_dinv[r0];
            ((float4*)d_ms1)[r0 * 8 + ttx] =
                make_float4(f2lo(acc[p][0]) * di, f2lo(acc[p][1]) * di,
                            f2lo(acc[p][2]) * di, f2lo(acc[p][3]) * di);
        }
        int r1 = r0 + 1;
        if (r1 < N) {
            float di = d_dinv[r1];
            ((float4*)d_ms1)[r1 * 8 + ttx] =
                make_float4(f2hi(acc[p][0]) * di, f2hi(acc[p][1]) * di,
                            f2hi(acc[p][2]) * di, f2hi(acc[p][3]) * di);
        }
    }
}

// ---------------- gather L1: 8 threads per node (32 cols) ------------------
__global__ __launch_bounds__(256) void k_gather1(int N) {
    int gt   = blockIdx.x * blockDim.x + threadIdx.x;
    int node = gt >> 3;
    int lane = gt & 7;
    if (node >= N) return;
    int s0 = __ldg(d_rowptr + node);
    int s1 = __ldg(d_rowptr + node + 1);
    const float4* M = (const float4*)d_ms1;
    float4 acc = __ldg(M + node * 8 + lane);
    int j = s0;
    for (; j + 1 < s1; j += 2) {
        int   a  = __ldg(d_csrc + j);
        int   b  = __ldg(d_csrc + j + 1);
        float wa = __ldg(d_cw + j);
        float wb = __ldg(d_cw + j + 1);
        float4 va = __ldg(M + a * 8 + lane);
        float4 vb = __ldg(M + b * 8 + lane);
        acc.x += va.x * wa + vb.x * wb;
        acc.y += va.y * wa + vb.y * wb;
        acc.z += va.z * wa + vb.z * wb;
        acc.w += va.w * wa + vb.w * wb;
    }
    if (j < s1) {
        int   a  = __ldg(d_csrc + j);
        float wa = __ldg(d_cw + j);
        float4 va = __ldg(M + a * 8 + lane);
        acc.x += va.x * wa; acc.y += va.y * wa;
        acc.z += va.z * wa; acc.w += va.w * wa;
    }
    float dn = __ldg(d_dinv + node);
    acc.x *= dn; acc.y *= dn; acc.z *= dn; acc.w *= dn;
    ((float4*)d_agg1)[node * 8 + lane] = acc;
}

// ---------------- pooling --------------------------------------------------
__global__ void k_gzero(int NG) {
    int i = blockIdx.x * blockDim.x + threadIdx.x;
    if (i < NG * 32) d_g[i] = 0.f;
}

__global__ void k_pool(const int* __restrict__ ngi,
                       const float* __restrict__ b1, int N) {
    int gt     = blockIdx.x * blockDim.x + threadIdx.x;
    int warpId = gt >> 5;
    int lane   = gt & 31;
    int chunk  = warpId & 7;
    int nodeBase = (warpId >> 3) << 5;
    int node   = nodeBase + lane;
    int c      = chunk << 2;

    float4 v = make_float4(0.f, 0.f, 0.f, 0.f);
    int gi = -1;
    if (node < N) {
        gi = __ldg(ngi + node);
        float4 a  = *(const float4*)(d_agg1 + node * 32 + c);
        float4 bb = __ldg((const float4*)b1 + chunk);
        v.x = fmaxf(a.x + bb.x, 0.f);
        v.y = fmaxf(a.y + bb.y, 0.f);
        v.z = fmaxf(a.z + bb.z, 0.f);
        v.w = fmaxf(a.w + bb.w, 0.f);
    }
    int gi0  = __shfl_sync(0xffffffffu, gi, 0);
    int gi31 = __shfl_sync(0xffffffffu, gi, 31);
    if (gi0 == gi31 && gi0 >= 0) {
#pragma unroll
        for (int off = 16; off; off >>= 1) {
            v.x += __shfl_xor_sync(0xffffffffu, v.x, off);
            v.y += __shfl_xor_sync(0xffffffffu, v.y, off);
            v.z += __shfl_xor_sync(0xffffffffu, v.z, off);
            v.w += __shfl_xor_sync(0xffffffffu, v.w, off);
        }
        if (lane == 0) red_add_v4(d_g + gi0 * 32 + c, v);
    } else if (gi >= 0) {
        red_add_v4(d_g + gi * 32 + c, v);
    }
}

// ---------------- MLP head -------------------------------------------------
__global__ __launch_bounds__(128) void k_mlp(const float* __restrict__ Wm1,
                                             const float* __restrict__ bm1,
                                             const float* __restrict__ Wm2,
                                             const float* __restrict__ bm2,
                                             float* __restrict__ out) {
    __shared__ float gs[32];
    __shared__ float hs[128];
    int gr = blockIdx.x;
    int t  = threadIdx.x;
    if (t < 32) gs[t] = d_g[gr * 32 + t];
    __syncthreads();
    float acc = __ldg(bm1 + t);
#pragma unroll
    for (int k = 0; k < 32; k++) acc += gs[k] * __ldg(Wm1 + k * 128 + t);
    hs[t] = fmaxf(acc, 0.f);
    __syncthreads();
    if (t < 2) {
        float a = __ldg(bm2 + t);
#pragma unroll 8
        for (int k = 0; k < 128; k++) a += hs[k] * __ldg(Wm2 + k * 2 + t);
        out[gr * 2 + t] = a;
    }
}

// ---------------------------------------------------------------------------
extern "C" void kernel_launch(void* const* d_in, const int* in_sizes, int n_in,
                              void* d_out, int out_size) {
    const float* x   = (const float*)d_in[0];
    const int*   ei  = (const int*)d_in[1];
    const float* ew  = (const float*)d_in[2];
    const int*   ngi = (const int*)d_in[3];
    const float* W0  = (const float*)d_in[4];
    const float* b0  = (const float*)d_in[5];
    const float* W1  = (const float*)d_in[6];
    const float* b1  = (const float*)d_in[7];
    const float* Wm1 = (const float*)d_in[8];
    const float* bm1 = (const float*)d_in[9];
    const float* Wm2 = (const float*)d_in[10];
    const float* bm2 = (const float*)d_in[11];
    float* out = (float*)d_out;

    int N  = in_sizes[0] / 128;
    int E  = in_sizes[2];
    int NG = out_size / 2;
    const int* src = ei;
    const int* dst = ei + E;
    int NB = (N + 1023) / 1024;

    // CSR build
    k_zero_cnt<<<(N + 255) / 256, 256>>>(N);
    k_hist    <<<(E + 255) / 256, 256>>>(dst, E);
    k_scanA   <<<NB, 1024>>>(N);
    k_scanB   <<<1, MAXNB>>>(NB);
    k_scanC   <<<NB, 1024>>>(N);
    k_fill    <<<(E + 255) / 256, 256>>>(src, dst, ew, E);
    k_deg     <<<(N + 255) / 256, 256>>>(N);

    // layer 0
    k_gemm0  <<<(N + 127) / 128, 256>>>(x, W0, N);
    k_gather0<<<(N * 16 + 255) / 256, 256>>>(N);

    // layer 1
    k_gemm1  <<<(N + 255) / 256, 256>>>(b0, W1, N);
    k_gather1<<<(N * 8 + 255) / 256, 256>>>(N);

    // pool + MLP
    k_gzero<<<(NG * 32 + 255) / 256, 256>>>(NG);
    int warps = ((N + 31) / 32) * 8;
    k_pool <<<(warps * 32 + 255) / 256, 256>>>(ngi, b1, N);
    k_mlp<<<NG, 128>>>(Wm1, bm1, Wm2, bm2, out);
}

// round 12
// speedup vs baseline: 1.4645x; 1.0161x over previous
#include <cuda_runtime.h>

// ---------------------------------------------------------------------------
// GCN: h0 = relu(Â x W0 + b0); h1 = relu(Â h0 W1 + b1);
//      g = segment_sum(h1, graph); logits = relu(g Wm1 + bm1) Wm2 + bm2
// Â = D^-1/2 (A+I) D^-1/2.
// Known-passing CSR-gather structure (r4) + minimal deltas:
//   int2-packed CSR, pool fused into gather1, merged zero kernel.
// ---------------------------------------------------------------------------

#define MAXN 100000
#define MAXE 1600000
#define MAXG 1000
#define MAXNB 128   // scan blocks: ceil(MAXN/1024)

__device__ int   d_cnt   [MAXN];
__device__ int   d_scan  [MAXN];
__device__ int   d_bsum  [MAXNB];
__device__ int   d_bscan [MAXNB];
__device__ int   d_rowptr[MAXN + 1];
__device__ int   d_cursor[MAXN];
__device__ int2  d_csr   [MAXE];      // {src, weight bits} per in-edge (dst-CSR)
__device__ float d_dinv  [MAXN];
__device__ float d_ms0   [MAXN * 64]; // (x@W0)*dinv
__device__ float d_agg0  [MAXN * 64];
__device__ float d_ms1   [MAXN * 32]; // (h0@W1)*dinv
__device__ float d_g     [MAXG * 32];

__device__ __forceinline__ void red_add_v4(float* addr, float4 v) {
    asm volatile("red.global.add.v4.f32 [%0], {%1, %2, %3, %4};"
                 :: "l"(addr), "f"(v.x), "f"(v.y), "f"(v.z), "f"(v.w)
                 : "memory");
}

#define FMA2(d, a, b) \
    asm("fma.rn.f32x2 %0, %1, %2, %0;" : "+l"(d) : "l"(a), "l"(b))

__device__ __forceinline__ float f2lo(unsigned long long v) {
    return __uint_as_float((unsigned)v);
}
__device__ __forceinline__ float f2hi(unsigned long long v) {
    return __uint_as_float((unsigned)(v >> 32));
}
__device__ __forceinline__ unsigned long long rep2(float f) {
    unsigned long long r;
    asm("mov.b64 %0, {%1, %1};" : "=l"(r) : "r"(__float_as_uint(f)));
    return r;
}

// ---------------- zero (capture-safe) --------------------------------------
__global__ void k_zero(int N, int NG32) {
    int i = blockIdx.x * blockDim.x + threadIdx.x;
    if (i < N) d_cnt[i] = 0;
    if (i < NG32) d_g[i] = 0.f;
}

// ---------------- CSR build ----------------
__global__ void k_hist(const int* __restrict__ dst, int E) {
    int e = blockIdx.x * blockDim.x + threadIdx.x;
    if (e < E) atomicAdd(&d_cnt[__ldg(dst + e)], 1);
}

__global__ __launch_bounds__(1024) void k_scanA(int N) {
    __shared__ int sh[1024];
    int i = blockIdx.x * 1024 + threadIdx.x;
    int v = (i < N) ? d_cnt[i] : 0;
    sh[threadIdx.x] = v;
    __syncthreads();
#pragma unroll
    for (int off = 1; off < 1024; off <<= 1) {
        int t = (threadIdx.x >= off) ? sh[threadIdx.x - off] : 0;
        __syncthreads();
        sh[threadIdx.x] += t;
        __syncthreads();
    }
    if (i < N) d_scan[i] = sh[threadIdx.x];
    if (threadIdx.x == 1023) d_bsum[blockIdx.x] = sh[1023];
}

__global__ __launch_bounds__(MAXNB) void k_scanB(int NB) {
    __shared__ int sh[MAXNB];
    int v = (threadIdx.x < NB) ? d_bsum[threadIdx.x] : 0;
    sh[threadIdx.x] = v;
    __syncthreads();
#pragma unroll
    for (int off = 1; off < MAXNB; off <<= 1) {
        int t = (threadIdx.x >= off) ? sh[threadIdx.x - off] : 0;
        __syncthreads();
        sh[threadIdx.x] += t;
        __syncthreads();
    }
    if (threadIdx.x < NB) d_bscan[threadIdx.x] = sh[threadIdx.x] - v;  // exclusive
}

__global__ __launch_bounds__(1024) void k_scanC(int N) {
    int i = blockIdx.x * 1024 + threadIdx.x;
    if (i < N) {
        int incl = d_scan[i] + d_bscan[blockIdx.x];
        d_rowptr[i + 1] = incl;
        d_cursor[i] = incl - d_cnt[i];
        if (i == 0) d_rowptr[0] = 0;
    }
}

__global__ void k_fill(const int* __restrict__ src,
                       const int* __restrict__ dst,
                       const float* __restrict__ w, int E) {
    int e = blockIdx.x * blockDim.x + threadIdx.x;
    if (e < E) {
        int d = __ldg(dst + e);
        int pos = atomicAdd(&d_cursor[d], 1);
        int2 pk;
        pk.x = __ldg(src + e);
        pk.y = __float_as_int(__ldg(w + e));
        d_csr[pos] = pk;
    }
}

// deg[i] = 1 + sum of in-edge weights (CSR-resident, sequential reads)
__global__ void k_deg(int N) {
    int i = blockIdx.x * blockDim.x + threadIdx.x;
    if (i < N) {
        int s = d_rowptr[i], t = d_rowptr[i + 1];
        float acc = 1.0f;
        for (int j = s; j < t; j++) acc += __int_as_float(__ldg(&d_csr[j].y));
        d_dinv[i] = rsqrtf(fmaxf(acc, 1e-12f));
    }
}

// ---------------- GEMM0: ms0 = (x @ W0) * dinv ----------------------------
// Tile 128 rows x 64 cols, 256 threads, FFMA2 row-pairs.
__global__ __launch_bounds__(256) void k_gemm0(const float* __restrict__ x,
                                               const float* __restrict__ W,
                                               int N) {
    __shared__ float XsT[32][132];
    int tid  = threadIdx.x;
    int row0 = blockIdx.x * 128;
    int ttx  = tid & 15;
    int tty  = tid >> 4;
    unsigned abase = (unsigned)__cvta_generic_to_shared(XsT) + tty * 32;

    unsigned long long acc[4][4];
#pragma unroll
    for (int p = 0; p < 4; p++)
#pragma unroll
        for (int c = 0; c < 4; c++) acc[p][c] = 0ull;

    const float4* x4 = (const float4*)x;
    const float4* W4 = (const float4*)W;

    for (int kc = 0; kc < 4; kc++) {
#pragma unroll
        for (int i = 0; i < 4; i++) {
            int v  = tid + 256 * i;
            int rl = v >> 3;
            int c4 = v & 7;
            int row = row0 + rl;
            float4 val = (row < N) ? __ldg(x4 + row * 32 + kc * 8 + c4)
                                   : make_float4(0.f, 0.f, 0.f, 0.f);
            XsT[c4 * 4 + 0][rl] = val.x;
            XsT[c4 * 4 + 1][rl] = val.y;
            XsT[c4 * 4 + 2][rl] = val.z;
            XsT[c4 * 4 + 3][rl] = val.w;
        }
        __syncthreads();

#pragma unroll 4
        for (int k = 0; k < 32; k++) {
            unsigned long long a0, a1, a2, a3;
            unsigned adr = abase + (unsigned)(k * 132 * 4);
            asm("ld.shared.v2.u64 {%0, %1}, [%2];" : "=l"(a0), "=l"(a1) : "r"(adr));
            asm("ld.shared.v2.u64 {%0, %1}, [%2];" : "=l"(a2), "=l"(a3) : "r"(adr + 16));
            float4 b = __ldg(W4 + (kc * 32 + k) * 16 + ttx);
            unsigned long long bx = rep2(b.x), by = rep2(b.y),
                               bz = rep2(b.z), bw = rep2(b.w);
            FMA2(acc[0][0], a0, bx); FMA2(acc[0][1], a0, by);
            FMA2(acc[0][2], a0, bz); FMA2(acc[0][3], a0, bw);
            FMA2(acc[1][0], a1, bx); FMA2(acc[1][1], a1, by);
            FMA2(acc[1][2], a1, bz); FMA2(acc[1][3], a1, bw);
            FMA2(acc[2][0], a2, bx); FMA2(acc[2][1], a2, by);
            FMA2(acc[2][2], a2, bz); FMA2(acc[2][3], a2, bw);
            FMA2(acc[3][0], a3, bx); FMA2(acc[3][1], a3, by);
            FMA2(acc[3][2], a3, bz); FMA2(acc[3][3], a3, bw);
        }
        __syncthreads();
    }

#pragma unroll
    for (int p = 0; p < 4; p++) {
        int r0 = row0 + tty * 8 + 2 * p;
        if (r0 < N) {
            float di = d_dinv[r0];
            ((float4*)d_ms0)[r0 * 16 + ttx] =
                make_float4(f2lo(acc[p][0]) * di, f2lo(acc[p][1]) * di,
                            f2lo(acc[p][2]) * di, f2lo(acc[p][3]) * di);
        }
        int r1 = r0 + 1;
        if (r1 < N) {
            float di = d_dinv[r1];
            ((float4*)d_ms0)[r1 * 16 + ttx] =
                make_float4(f2hi(acc[p][0]) * di, f2hi(acc[p][1]) * di,
                            f2hi(acc[p][2]) * di, f2hi(acc[p][3]) * di);
        }
    }
}

// ---------------- gather L0: agg0[d] = dinv[d]*(ms0[d] + sum ms0[s]*w) -----
__global__ __launch_bounds__(256) void k_gather0(int N) {
    int gt   = blockIdx.x * blockDim.x + threadIdx.x;
    int node = gt >> 4;
    int lane = gt & 15;
    if (node >= N) return;
    int s0 = __ldg(d_rowptr + node);
    int s1 = __ldg(d_rowptr + node + 1);
    const float4* M = (const float4*)d_ms0;
    float4 acc = __ldg(M + node * 16 + lane);
    int j = s0;
    for (; j + 1 < s1; j += 2) {
        int2 ea = __ldg(d_csr + j);
        int2 eb = __ldg(d_csr + j + 1);
        float wa = __int_as_float(ea.y);
        float wb = __int_as_float(eb.y);
        float4 va = __ldg(M + ea.x * 16 + lane);
        float4 vb = __ldg(M + eb.x * 16 + lane);
        acc.x += va.x * wa + vb.x * wb;
        acc.y += va.y * wa + vb.y * wb;
        acc.z += va.z * wa + vb.z * wb;
        acc.w += va.w * wa + vb.w * wb;
    }
    if (j < s1) {
        int2 ea = __ldg(d_csr + j);
        float wa = __int_as_float(ea.y);
        float4 va = __ldg(M + ea.x * 16 + lane);
        acc.x += va.x * wa; acc.y += va.y * wa;
        acc.z += va.z * wa; acc.w += va.w * wa;
    }
    float dn = __ldg(d_dinv + node);
    acc.x *= dn; acc.y *= dn; acc.z *= dn; acc.w *= dn;
    ((float4*)d_agg0)[node * 16 + lane] = acc;
}

// ---------------- GEMM1: ms1 = (relu(agg0+b0) @ W1) * dinv -----------------
__global__ __launch_bounds__(256) void k_gemm1(const float* __restrict__ b0,
                                               const float* __restrict__ W,
                                               int N) {
    __shared__ float XsT[32][260];
    int tid  = threadIdx.x;
    int row0 = blockIdx.x * 256;
    int ttx  = tid & 7;
    int tty  = tid >> 3;
    unsigned abase = (unsigned)__cvta_generic_to_shared(XsT) + tty * 32;

    unsigned long long acc[4][4];
#pragma unroll
    for (int p = 0; p < 4; p++)
#pragma unroll
        for (int c = 0; c < 4; c++) acc[p][c] = 0ull;

    const float4* A4  = (const float4*)d_agg0;
    const float4* W4  = (const float4*)W;
    const float4* bb4 = (const float4*)b0;

    for (int kc = 0; kc < 2; kc++) {
#pragma unroll
        for (int i = 0; i < 8; i++) {
            int v  = tid + 256 * i;
            int rl = v >> 3;
            int c4 = v & 7;
            int row = row0 + rl;
            float4 val = (row < N) ? A4[row * 16 + kc * 8 + c4]
                                   : make_float4(0.f, 0.f, 0.f, 0.f);
            float4 bv = __ldg(bb4 + kc * 8 + c4);
            XsT[c4 * 4 + 0][rl] = fmaxf(val.x + bv.x, 0.f);
            XsT[c4 * 4 + 1][rl] = fmaxf(val.y + bv.y, 0.f);
            XsT[c4 * 4 + 2][rl] = fmaxf(val.z + bv.z, 0.f);
            XsT[c4 * 4 + 3][rl] = fmaxf(val.w + bv.w, 0.f);
        }
        __syncthreads();

#pragma unroll 4
        for (int k = 0; k < 32; k++) {
            unsigned long long a0, a1, a2, a3;
            unsigned adr = abase + (unsigned)(k * 260 * 4);
            asm("ld.shared.v2.u64 {%0, %1}, [%2];" : "=l"(a0), "=l"(a1) : "r"(adr));
            asm("ld.shared.v2.u64 {%0, %1}, [%2];" : "=l"(a2), "=l"(a3) : "r"(adr + 16));
            float4 b = __ldg(W4 + (kc * 32 + k) * 8 + ttx);
            unsigned long long bx = rep2(b.x), by = rep2(b.y),
                               bz = rep2(b.z), bw = rep2(b.w);
            FMA2(acc[0][0], a0, bx); FMA2(acc[0][1], a0, by);
            FMA2(acc[0][2], a0, bz); FMA2(acc[0][3], a0, bw);
            FMA2(acc[1][0], a1, bx); FMA2(acc[1][1], a1, by);
            FMA2(acc[1][2], a1, bz); FMA2(acc[1][3], a1, bw);
            FMA2(acc[2][0], a2, bx); FMA2(acc[2][1], a2, by);
            FMA2(acc[2][2], a2, bz); FMA2(acc[2][3], a2, bw);
            FMA2(acc[3][0], a3, bx); FMA2(acc[3][1], a3, by);
            FMA2(acc[3][2], a3, bz); FMA2(acc[3][3], a3, bw);
        }
        __syncthreads();
    }

#pragma unroll
    for (int p = 0; p < 4; p++) {
        int r0 = row0 + tty * 8 + 2 * p;
        if (r0 < N) {
            float di = d_dinv[r0];
            ((float4*)d_ms1)[r0 * 8 + ttx] =
                make_float4(f2lo(acc[p][0]) * di, f2lo(acc[p][1]) * di,
                            f2lo(acc[p][2]) * di, f2lo(acc[p][3]) * di);
        }
        int r1 = r0 + 1;
        if (r1 < N) {
            float di = d_dinv[r1];
            ((float4*)d_ms1)[r1 * 8 + ttx] =
                make_float4(f2hi(acc[p][0]) * di, f2hi(acc[p][1]) * di,
                            f2hi(acc[p][2]) * di, f2hi(acc[p][3]) * di);
        }
    }
}

// ---------------- gather L1 + pool (fused) ---------------------------------
// 8 lanes per node; warp covers 4 consecutive nodes. relu(agg1+b1) pooled
// straight into d_g with warp-level pre-reduction when graph-uniform.
__global__ __launch_bounds__(256) void k_gather1_pool(const int* __restrict__ ngi,
                                                      const float* __restrict__ b1,
                                                      int N) {
    int gt   = blockIdx.x * blockDim.x + threadIdx.x;
    int node = gt >> 3;
    int lane = gt & 7;
    int wl   = threadIdx.x & 31;

    float4 acc = make_float4(0.f, 0.f, 0.f, 0.f);
    int gi = -1;
    if (node < N) {
        int s0 = __ldg(d_rowptr + node);
        int s1 = __ldg(d_rowptr + node + 1);
        const float4* M = (const float4*)d_ms1;
        acc = __ldg(M + node * 8 + lane);
        int j = s0;
        for (; j + 1 < s1; j += 2) {
            int2 ea = __ldg(d_csr + j);
            int2 eb = __ldg(d_csr + j + 1);
            float wa = __int_as_float(ea.y);
            float wb = __int_as_float(eb.y);
            float4 va = __ldg(M + ea.x * 8 + lane);
            float4 vb = __ldg(M + eb.x * 8 + lane);
            acc.x += va.x * wa + vb.x * wb;
            acc.y += va.y * wa + vb.y * wb;
            acc.z += va.z * wa + vb.z * wb;
            acc.w += va.w * wa + vb.w * wb;
        }
        if (j < s1) {
            int2 ea = __ldg(d_csr + j);
            float wa = __int_as_float(ea.y);
            float4 va = __ldg(M + ea.x * 8 + lane);
            acc.x += va.x * wa; acc.y += va.y * wa;
            acc.z += va.z * wa; acc.w += va.w * wa;
        }
        float dn = __ldg(d_dinv + node);
        float4 bb = __ldg((const float4*)b1 + lane);
        acc.x = fmaxf(acc.x * dn + bb.x, 0.f);
        acc.y = fmaxf(acc.y * dn + bb.y, 0.f);
        acc.z = fmaxf(acc.z * dn + bb.z, 0.f);
        acc.w = fmaxf(acc.w * dn + bb.w, 0.f);
        gi = __ldg(ngi + node);
    }

    int gi0  = __shfl_sync(0xffffffffu, gi, 0);
    int gi31 = __shfl_sync(0xffffffffu, gi, 31);
    if (gi0 == gi31 && gi0 >= 0) {
        // all 4 nodes in this warp belong to the same graph: reduce across
        // the 4 node-slots (xor 8, xor 16), lanes 0-7 hold cols 0..31.
        acc.x += __shfl_xor_sync(0xffffffffu, acc.x, 8);
        acc.y += __shfl_xor_sync(0xffffffffu, acc.y, 8);
        acc.z += __shfl_xor_sync(0xffffffffu, acc.z, 8);
        acc.w += __shfl_xor_sync(0xffffffffu, acc.w, 8);
        acc.x += __shfl_xor_sync(0xffffffffu, acc.x, 16);
        acc.y += __shfl_xor_sync(0xffffffffu, acc.y, 16);
        acc.z += __shfl_xor_sync(0xffffffffu, acc.z, 16);
        acc.w += __shfl_xor_sync(0xffffffffu, acc.w, 16);
        if (wl < 8) red_add_v4(d_g + gi0 * 32 + wl * 4, acc);
    } else if (gi >= 0) {
        red_add_v4(d_g + gi * 32 + lane * 4, acc);
    }
}

// ---------------- MLP head -------------------------------------------------
__global__ __launch_bounds__(128) void k_mlp(const float* __restrict__ Wm1,
                                             const float* __restrict__ bm1,
                                             const float* __restrict__ Wm2,
                                             const float* __restrict__ bm2,
                                             float* __restrict__ out) {
    __shared__ float gs[32];
    __shared__ float hs[128];
    int gr = blockIdx.x;
    int t  = threadIdx.x;
    if (t < 32) gs[t] = d_g[gr * 32 + t];
    __syncthreads();
    float acc = __ldg(bm1 + t);
#pragma unroll
    for (int k = 0; k < 32; k++) acc += gs[k] * __ldg(Wm1 + k * 128 + t);
    hs[t] = fmaxf(acc, 0.f);
    __syncthreads();
    if (t < 2) {
        float a = __ldg(bm2 + t);
#pragma unroll 8
        for (int k = 0; k < 128; k++) a += hs[k] * __ldg(Wm2 + k * 2 + t);
        out[gr * 2 + t] = a;
    }
}

// ---------------------------------------------------------------------------
extern "C" void kernel_launch(void* const* d_in, const int* in_sizes, int n_in,
                              void* d_out, int out_size) {
    const float* x   = (const float*)d_in[0];
    const int*   ei  = (const int*)d_in[1];
    const float* ew  = (const float*)d_in[2];
    const int*   ngi = (const int*)d_in[3];
    const float* W0  = (const float*)d_in[4];
    const float* b0  = (const float*)d_in[5];
    const float* W1  = (const float*)d_in[6];
    const float* b1  = (const float*)d_in[7];
    const float* Wm1 = (const float*)d_in[8];
    const float* bm1 = (const float*)d_in[9];
    const float* Wm2 = (const float*)d_in[10];
    const float* bm2 = (const float*)d_in[11];
    float* out = (float*)d_out;

    int N  = in_sizes[0] / 128;
    int E  = in_sizes[2];
    int NG = out_size / 2;
    const int* src = ei;
    const int* dst = ei + E;
    int NB = (N + 1023) / 1024;

    int zmax = (N > NG * 32) ? N : NG * 32;
    k_zero <<<(zmax + 255) / 256, 256>>>(N, NG * 32);

    // CSR build
    k_hist <<<(E + 255) / 256, 256>>>(dst, E);
    k_scanA<<<NB, 1024>>>(N);
    k_scanB<<<1, MAXNB>>>(NB);
    k_scanC<<<NB, 1024>>>(N);
    k_fill <<<(E + 255) / 256, 256>>>(src, dst, ew, E);
    k_deg  <<<(N + 255) / 256, 256>>>(N);

    // layer 0
    k_gemm0  <<<(N + 127) / 128, 256>>>(x, W0, N);
    k_gather0<<<(N * 16 + 255) / 256, 256>>>(N);

    // layer 1
    k_gemm1       <<<(N + 255) / 256, 256>>>(b0, W1, N);
    k_gather1_pool<<<(N * 8 + 255) / 256, 256>>>(ngi, b1, N);

    k_mlp<<<NG, 128>>>(Wm1, bm1, Wm2, bm2, out);
}

// round 14
// speedup vs baseline: 1.5551x; 1.0618x over previous
#include <cuda_runtime.h>

// ---------------------------------------------------------------------------
// GCN: h0 = relu(Â x W0 + b0); h1 = relu(Â h0 W1 + b1);
//      g = segment_sum(h1, graph); logits = relu(g Wm1 + bm1) Wm2 + bm2
// Â = D^-1/2 (A+I) D^-1/2.
// CSR-gather structure; deltas this round: scanB folded into scanC,
// degree computation folded into gemm0 prologue (latency-hidden).
// ---------------------------------------------------------------------------

#define MAXN 100000
#define MAXE 1600000
#define MAXG 1000
#define MAXNB 128   // scan blocks: ceil(MAXN/1024)

__device__ int   d_cnt   [MAXN];
__device__ int   d_scan  [MAXN];
__device__ int   d_bsum  [MAXNB];
__device__ int   d_rowptr[MAXN + 1];
__device__ int   d_cursor[MAXN];
__device__ int2  d_csr   [MAXE];      // {src, weight bits} per in-edge (dst-CSR)
__device__ float d_dinv  [MAXN];
__device__ float d_ms0   [MAXN * 64]; // (x@W0)*dinv
__device__ float d_agg0  [MAXN * 64];
__device__ float d_ms1   [MAXN * 32]; // (h0@W1)*dinv
__device__ float d_g     [MAXG * 32];

__device__ __forceinline__ void red_add_v4(float* addr, float4 v) {
    asm volatile("red.global.add.v4.f32 [%0], {%1, %2, %3, %4};"
                 :: "l"(addr), "f"(v.x), "f"(v.y), "f"(v.z), "f"(v.w)
                 : "memory");
}

#define FMA2(d, a, b) \
    asm("fma.rn.f32x2 %0, %1, %2, %0;" : "+l"(d) : "l"(a), "l"(b))

__device__ __forceinline__ float f2lo(unsigned long long v) {
    return __uint_as_float((unsigned)v);
}
__device__ __forceinline__ float f2hi(unsigned long long v) {
    return __uint_as_float((unsigned)(v >> 32));
}
__device__ __forceinline__ unsigned long long rep2(float f) {
    unsigned long long r;
    asm("mov.b64 %0, {%1, %1};" : "=l"(r) : "r"(__float_as_uint(f)));
    return r;
}

// ---------------- zero (capture-safe) --------------------------------------
__global__ void k_zero(int N, int NG32) {
    int i = blockIdx.x * blockDim.x + threadIdx.x;
    if (i < N) d_cnt[i] = 0;
    if (i < NG32) d_g[i] = 0.f;
}

// ---------------- CSR build ----------------
__global__ void k_hist(const int* __restrict__ dst, int E) {
    int e = blockIdx.x * blockDim.x + threadIdx.x;
    if (e < E) atomicAdd(&d_cnt[__ldg(dst + e)], 1);
}

__global__ __launch_bounds__(1024) void k_scanA(int N) {
    __shared__ int sh[1024];
    int i = blockIdx.x * 1024 + threadIdx.x;
    int v = (i < N) ? d_cnt[i] : 0;
    sh[threadIdx.x] = v;
    __syncthreads();
#pragma unroll
    for (int off = 1; off < 1024; off <<= 1) {
        int t = (threadIdx.x >= off) ? sh[threadIdx.x - off] : 0;
        __syncthreads();
        sh[threadIdx.x] += t;
        __syncthreads();
    }
    if (i < N) d_scan[i] = sh[threadIdx.x];
    if (threadIdx.x == 1023) d_bsum[blockIdx.x] = sh[1023];
}

// scanC with in-kernel prefix over block sums (scanB folded in).
__global__ __launch_bounds__(1024) void k_scanC(int N) {
    __shared__ int pre;
    if (threadIdx.x < 32) {
        int s = 0;
        for (int t = threadIdx.x; t < (int)blockIdx.x; t += 32) s += d_bsum[t];
#pragma unroll
        for (int off = 16; off; off >>= 1)
            s += __shfl_xor_sync(0xffffffffu, s, off);
        if (threadIdx.x == 0) pre = s;
    }
    __syncthreads();
    int i = blockIdx.x * 1024 + threadIdx.x;
    if (i < N) {
        int incl = d_scan[i] + pre;
        d_rowptr[i + 1] = incl;
        d_cursor[i] = incl - d_cnt[i];
        if (i == 0) d_rowptr[0] = 0;
    }
}

__global__ void k_fill(const int* __restrict__ src,
                       const int* __restrict__ dst,
                       const float* __restrict__ w, int E) {
    int e = blockIdx.x * blockDim.x + threadIdx.x;
    if (e < E) {
        int d = __ldg(dst + e);
        int pos = atomicAdd(&d_cursor[d], 1);
        int2 pk;
        pk.x = __ldg(src + e);
        pk.y = __float_as_int(__ldg(w + e));
        d_csr[pos] = pk;
    }
}

// ---------------- GEMM0: ms0 = (x @ W0) * dinv;  deg fused in prologue -----
// Tile 128 rows x 64 cols, 256 threads, FFMA2 row-pairs.
__global__ __launch_bounds__(256) void k_gemm0(const float* __restrict__ x,
                                               const float* __restrict__ W,
                                               int N) {
    __shared__ float XsT[32][132];
    __shared__ float sh_dinv[128];
    int tid  = threadIdx.x;
    int row0 = blockIdx.x * 128;
    int ttx  = tid & 15;
    int tty  = tid >> 4;
    unsigned abase = (unsigned)__cvta_generic_to_shared(XsT) + tty * 32;

    // degree for this block's 128 rows; loads overlap the whole GEMM below.
    if (tid < 128) {
        int row = row0 + tid;
        float dacc = 1.0f;
        if (row < N) {
            int s = __ldg(d_rowptr + row), t = __ldg(d_rowptr + row + 1);
            for (int j = s; j < t; j++)
                dacc += __int_as_float(__ldg(&d_csr[j].y));
        }
        float di = rsqrtf(fmaxf(dacc, 1e-12f));
        sh_dinv[tid] = di;
        if (row < N) d_dinv[row] = di;
    }

    unsigned long long acc[4][4];
#pragma unroll
    for (int p = 0; p < 4; p++)
#pragma unroll
        for (int c = 0; c < 4; c++) acc[p][c] = 0ull;

    const float4* x4 = (const float4*)x;
    const float4* W4 = (const float4*)W;

    for (int kc = 0; kc < 4; kc++) {
#pragma unroll
        for (int i = 0; i < 4; i++) {
            int v  = tid + 256 * i;
            int rl = v >> 3;
            int c4 = v & 7;
            int row = row0 + rl;
            float4 val = (row < N) ? __ldg(x4 + row * 32 + kc * 8 + c4)
                                   : make_float4(0.f, 0.f, 0.f, 0.f);
            XsT[c4 * 4 + 0][rl] = val.x;
            XsT[c4 * 4 + 1][rl] = val.y;
            XsT[c4 * 4 + 2][rl] = val.z;
            XsT[c4 * 4 + 3][rl] = val.w;
        }
        __syncthreads();

#pragma unroll 4
        for (int k = 0; k < 32; k++) {
            unsigned long long a0, a1, a2, a3;
            unsigned adr = abase + (unsigned)(k * 132 * 4);
            asm("ld.shared.v2.u64 {%0, %1}, [%2];" : "=l"(a0), "=l"(a1) : "r"(adr));
            asm("ld.shared.v2.u64 {%0, %1}, [%2];" : "=l"(a2), "=l"(a3) : "r"(adr + 16));
            float4 b = __ldg(W4 + (kc * 32 + k) * 16 + ttx);
            unsigned long long bx = rep2(b.x), by = rep2(b.y),
                               bz = rep2(b.z), bw = rep2(b.w);
            FMA2(acc[0][0], a0, bx); FMA2(acc[0][1], a0, by);
            FMA2(acc[0][2], a0, bz); FMA2(acc[0][3], a0, bw);
            FMA2(acc[1][0], a1, bx); FMA2(acc[1][1], a1, by);
            FMA2(acc[1][2], a1, bz); FMA2(acc[1][3], a1, bw);
            FMA2(acc[2][0], a2, bx); FMA2(acc[2][1], a2, by);
            FMA2(acc[2][2], a2, bz); FMA2(acc[2][3], a2, bw);
            FMA2(acc[3][0], a3, bx); FMA2(acc[3][1], a3, by);
            FMA2(acc[3][2], a3, bz); FMA2(acc[3][3], a3, bw);
        }
        __syncthreads();
    }

#pragma unroll
    for (int p = 0; p < 4; p++) {
        int r0 = row0 + tty * 8 + 2 * p;
        if (r0 < N) {
            float di = sh_dinv[tty * 8 + 2 * p];
            ((float4*)d_ms0)[r0 * 16 + ttx] =
                make_float4(f2lo(acc[p][0]) * di, f2lo(acc[p][1]) * di,
                            f2lo(acc[p][2]) * di, f2lo(acc[p][3]) * di);
        }
        int r1 = r0 + 1;
        if (r1 < N) {
            float di = sh_dinv[tty * 8 + 2 * p + 1];
            ((float4*)d_ms0)[r1 * 16 + ttx] =
                make_float4(f2hi(acc[p][0]) * di, f2hi(acc[p][1]) * di,
                            f2hi(acc[p][2]) * di, f2hi(acc[p][3]) * di);
        }
    }
}

// ---------------- gather L0: agg0[d] = dinv[d]*(ms0[d] + sum ms0[s]*w) -----
__global__ __launch_bounds__(256) void k_gather0(int N) {
    int gt   = blockIdx.x * blockDim.x + threadIdx.x;
    int node = gt >> 4;
    int lane = gt & 15;
    if (node >= N) return;
    int s0 = __ldg(d_rowptr + node);
    int s1 = __ldg(d_rowptr + node + 1);
    const float4* M = (const float4*)d_ms0;
    float4 acc = __ldg(M + node * 16 + lane);
    int j = s0;
    for (; j + 1 < s1; j += 2) {
        int2 ea = __ldg(d_csr + j);
        int2 eb = __ldg(d_csr + j + 1);
        float wa = __int_as_float(ea.y);
        float wb = __int_as_float(eb.y);
        float4 va = __ldg(M + ea.x * 16 + lane);
        float4 vb = __ldg(M + eb.x * 16 + lane);
        acc.x += va.x * wa + vb.x * wb;
        acc.y += va.y * wa + vb.y * wb;
        acc.z += va.z * wa + vb.z * wb;
        acc.w += va.w * wa + vb.w * wb;
    }
    if (j < s1) {
        int2 ea = __ldg(d_csr + j);
        float wa = __int_as_float(ea.y);
        float4 va = __ldg(M + ea.x * 16 + lane);
        acc.x += va.x * wa; acc.y += va.y * wa;
        acc.z += va.z * wa; acc.w += va.w * wa;
    }
    float dn = __ldg(d_dinv + node);
    acc.x *= dn; acc.y *= dn; acc.z *= dn; acc.w *= dn;
    ((float4*)d_agg0)[node * 16 + lane] = acc;
}

// ---------------- GEMM1: ms1 = (relu(agg0+b0) @ W1) * dinv -----------------
__global__ __launch_bounds__(256) void k_gemm1(const float* __restrict__ b0,
                                               const float* __restrict__ W,
                                               int N) {
    __shared__ float XsT[32][260];
    int tid  = threadIdx.x;
    int row0 = blockIdx.x * 256;
    int ttx  = tid & 7;
    int tty  = tid >> 3;
    unsigned abase = (unsigned)__cvta_generic_to_shared(XsT) + tty * 32;

    unsigned long long acc[4][4];
#pragma unroll
    for (int p = 0; p < 4; p++)
#pragma unroll
        for (int c = 0; c < 4; c++) acc[p][c] = 0ull;

    const float4* A4  = (const float4*)d_agg0;
    const float4* W4  = (const float4*)W;
    const float4* bb4 = (const float4*)b0;

    for (int kc = 0; kc < 2; kc++) {
#pragma unroll
        for (int i = 0; i < 8; i++) {
            int v  = tid + 256 * i;
            int rl = v >> 3;
            int c4 = v & 7;
            int row = row0 + rl;
            float4 val = (row < N) ? A4[row * 16 + kc * 8 + c4]
                                   : make_float4(0.f, 0.f, 0.f, 0.f);
            float4 bv = __ldg(bb4 + kc * 8 + c4);
            XsT[c4 * 4 + 0][rl] = fmaxf(val.x + bv.x, 0.f);
            XsT[c4 * 4 + 1][rl] = fmaxf(val.y + bv.y, 0.f);
            XsT[c4 * 4 + 2][rl] = fmaxf(val.z + bv.z, 0.f);
            XsT[c4 * 4 + 3][rl] = fmaxf(val.w + bv.w, 0.f);
        }
        __syncthreads();

#pragma unroll 4
        for (int k = 0; k < 32; k++) {
            unsigned long long a0, a1, a2, a3;
            unsigned adr = abase + (unsigned)(k * 260 * 4);
            asm("ld.shared.v2.u64 {%0, %1}, [%2];" : "=l"(a0), "=l"(a1) : "r"(adr));
            asm("ld.shared.v2.u64 {%0, %1}, [%2];" : "=l"(a2), "=l"(a3) : "r"(adr + 16));
            float4 b = __ldg(W4 + (kc * 32 + k) * 8 + ttx);
            unsigned long long bx = rep2(b.x), by = rep2(b.y),
                               bz = rep2(b.z), bw = rep2(b.w);
            FMA2(acc[0][0], a0, bx); FMA2(acc[0][1], a0, by);
            FMA2(acc[0][2], a0, bz); FMA2(acc[0][3], a0, bw);
            FMA2(acc[1][0], a1, bx); FMA2(acc[1][1], a1, by);
            FMA2(acc[1][2], a1, bz); FMA2(acc[1][3], a1, bw);
            FMA2(acc[2][0], a2, bx); FMA2(acc[2][1], a2, by);
            FMA2(acc[2][2], a2, bz); FMA2(acc[2][3], a2, bw);
            FMA2(acc[3][0], a3, bx); FMA2(acc[3][1], a3, by);
            FMA2(acc[3][2], a3, bz); FMA2(acc[3][3], a3, bw);
        }
        __syncthreads();
    }

#pragma unroll
    for (int p = 0; p < 4; p++) {
        int r0 = row0 + tty * 8 + 2 * p;
        if (r0 < N) {
            float di = d_dinv[r0];
            ((float4*)d_ms1)[r0 * 8 + ttx] =
                make_float4(f2lo(acc[p][0]) * di, f2lo(acc[p][1]) * di,
                            f2lo(acc[p][2]) * di, f2lo(acc[p][3]) * di);
        }
        int r1 = r0 + 1;
        if (r1 < N) {
            float di = d_dinv[r1];
            ((float4*)d_ms1)[r1 * 8 + ttx] =
                make_float4(f2hi(acc[p][0]) * di, f2hi(acc[p][1]) * di,
                            f2hi(acc[p][2]) * di, f2hi(acc[p][3]) * di);
        }
    }
}

// ---------------- gather L1 + pool (fused) ---------------------------------
__global__ __launch_bounds__(256) void k_gather1_pool(const int* __restrict__ ngi,
                                                      const float* __restrict__ b1,
                                                      int N) {
    int gt   = blockIdx.x * blockDim.x + threadIdx.x;
    int node = gt >> 3;
    int lane = gt & 7;
    int wl   = threadIdx.x & 31;

    float4 acc = make_float4(0.f, 0.f, 0.f, 0.f);
    int gi = -1;
    if (node < N) {
        int s0 = __ldg(d_rowptr + node);
        int s1 = __ldg(d_rowptr + node + 1);
        const float4* M = (const float4*)d_ms1;
        acc = __ldg(M + node * 8 + lane);
        int j = s0;
        for (; j + 1 < s1; j += 2) {
            int2 ea = __ldg(d_csr + j);
            int2 eb = __ldg(d_csr + j + 1);
            float wa = __int_as_float(ea.y);
            float wb = __int_as_float(eb.y);
            float4 va = __ldg(M + ea.x * 8 + lane);
            float4 vb = __ldg(M + eb.x * 8 + lane);
            acc.x += va.x * wa + vb.x * wb;
            acc.y += va.y * wa + vb.y * wb;
            acc.z += va.z * wa + vb.z * wb;
            acc.w += va.w * wa + vb.w * wb;
        }
        if (j < s1) {
            int2 ea = __ldg(d_csr + j);
            float wa = __int_as_float(ea.y);
            float4 va = __ldg(M + ea.x * 8 + lane);
            acc.x += va.x * wa; acc.y += va.y * wa;
            acc.z += va.z * wa; acc.w += va.w * wa;
        }
        float dn = __ldg(d_dinv + node);
        float4 bb = __ldg((const float4*)b1 + lane);
        acc.x = fmaxf(acc.x * dn + bb.x, 0.f);
        acc.y = fmaxf(acc.y * dn + bb.y, 0.f);
        acc.z = fmaxf(acc.z * dn + bb.z, 0.f);
        acc.w = fmaxf(acc.w * dn + bb.w, 0.f);
        gi = __ldg(ngi + node);
    }

    int gi0  = __shfl_sync(0xffffffffu, gi, 0);
    int gi31 = __shfl_sync(0xffffffffu, gi, 31);
    if (gi0 == gi31 && gi0 >= 0) {
        acc.x += __shfl_xor_sync(0xffffffffu, acc.x, 8);
        acc.y += __shfl_xor_sync(0xffffffffu, acc.y, 8);
        acc.z += __shfl_xor_sync(0xffffffffu, acc.z, 8);
        acc.w += __shfl_xor_sync(0xffffffffu, acc.w, 8);
        acc.x += __shfl_xor_sync(0xffffffffu, acc.x, 16);
        acc.y += __shfl_xor_sync(0xffffffffu, acc.y, 16);
        acc.z += __shfl_xor_sync(0xffffffffu, acc.z, 16);
        acc.w += __shfl_xor_sync(0xffffffffu, acc.w, 16);
        if (wl < 8) red_add_v4(d_g + gi0 * 32 + wl * 4, acc);
    } else if (gi >= 0) {
        red_add_v4(d_g + gi * 32 + lane * 4, acc);
    }
}

// ---------------- MLP head -------------------------------------------------
__global__ __launch_bounds__(128) void k_mlp(const float* __restrict__ Wm1,
                                             const float* __restrict__ bm1,
                                             const float* __restrict__ Wm2,
                                             const float* __restrict__ bm2,
                                             float* __restrict__ out) {
    __shared__ float gs[32];
    __shared__ float hs[128];
    int gr = blockIdx.x;
    int t  = threadIdx.x;
    if (t < 32) gs[t] = d_g[gr * 32 + t];
    __syncthreads();
    float acc = __ldg(bm1 + t);
#pragma unroll
    for (int k = 0; k < 32; k++) acc += gs[k] * __ldg(Wm1 + k * 128 + t);
    hs[t] = fmaxf(acc, 0.f);
    __syncthreads();
    if (t < 2) {
        float a = __ldg(bm2 + t);
#pragma unroll 8
        for (int k = 0; k < 128; k++) a += hs[k] * __ldg(Wm2 + k * 2 + t);
        out[gr * 2 + t] = a;
    }
}

// ---------------------------------------------------------------------------
extern "C" void kernel_launch(void* const* d_in, const int* in_sizes, int n_in,
                              void* d_out, int out_size) {
    const float* x   = (const float*)d_in[0];
    const int*   ei  = (const int*)d_in[1];
    const float* ew  = (const float*)d_in[2];
    const int*   ngi = (const int*)d_in[3];
    const float* W0  = (const float*)d_in[4];
    const float* b0  = (const float*)d_in[5];
    const float* W1  = (const float*)d_in[6];
    const float* b1  = (const float*)d_in[7];
    const float* Wm1 = (const float*)d_in[8];
    const float* bm1 = (const float*)d_in[9];
    const float* Wm2 = (const float*)d_in[10];
    const float* bm2 = (const float*)d_in[11];
    float* out = (float*)d_out;

    int N  = in_sizes[0] / 128;
    int E  = in_sizes[2];
    int NG = out_size / 2;
    const int* src = ei;
    const int* dst = ei + E;
    int NB = (N + 1023) / 1024;

    int zmax = (N > NG * 32) ? N : NG * 32;
    k_zero <<<(zmax + 255) / 256, 256>>>(N, NG * 32);

    // CSR build
    k_hist <<<(E + 255) / 256, 256>>>(dst, E);
    k_scanA<<<NB, 1024>>>(N);
    k_scanC<<<NB, 1024>>>(N);
    k_fill <<<(E + 255) / 256, 256>>>(src, dst, ew, E);

    // layer 0 (deg fused into gemm0 prologue)
    k_gemm0  <<<(N + 127) / 128, 256>>>(x, W0, N);
    k_gather0<<<(N * 16 + 255) / 256, 256>>>(N);

    // layer 1
    k_gemm1       <<<(N + 255) / 256, 256>>>(b0, W1, N);
    k_gather1_pool<<<(N * 8 + 255) / 256, 256>>>(ngi, b1, N);

    k_mlp<<<NG, 128>>>(Wm1, bm1, Wm2, bm2, out);
}

// round 15
// speedup vs baseline: 1.6250x; 1.0450x over previous
#include <cuda_runtime.h>

// ---------------------------------------------------------------------------
// GCN: h0 = relu(Â x W0 + b0); h1 = relu(Â h0 W1 + b1);
//      g = segment_sum(h1, graph); logits = relu(g Wm1 + bm1) Wm2 + bm2
// Â = D^-1/2 (A+I) D^-1/2.
// This round: degree accumulated in k_hist (float red per edge), so CSR fill
// and GEMM0 are independent -> co-scheduled in one kernel (gemm blocks first).
// ---------------------------------------------------------------------------

#define MAXN 100000
#define MAXE 1600000
#define MAXG 1000

__device__ int   d_cnt   [MAXN];
__device__ int   d_scan  [MAXN];
__device__ int   d_bsum  [128];
__device__ int   d_rowptr[MAXN + 1];
__device__ int   d_cursor[MAXN];
__device__ int2  d_csr   [MAXE];      // {src, weight bits} per in-edge (dst-CSR)
__device__ float d_deg   [MAXN];      // 1 + sum in-weights (built by k_hist)
__device__ float d_dinv  [MAXN];
__device__ float d_ms0   [MAXN * 64]; // (x@W0)*dinv
__device__ float d_agg0  [MAXN * 64];
__device__ float d_ms1   [MAXN * 32]; // (h0@W1)*dinv
__device__ float d_g     [MAXG * 32];

__device__ __forceinline__ void red_add_v4(float* addr, float4 v) {
    asm volatile("red.global.add.v4.f32 [%0], {%1, %2, %3, %4};"
                 :: "l"(addr), "f"(v.x), "f"(v.y), "f"(v.z), "f"(v.w)
                 : "memory");
}

__device__ __forceinline__ void red_add_f32(float* addr, float v) {
    asm volatile("red.global.add.f32 [%0], %1;" :: "l"(addr), "f"(v) : "memory");
}

#define FMA2(d, a, b) \
    asm("fma.rn.f32x2 %0, %1, %2, %0;" : "+l"(d) : "l"(a), "l"(b))

__device__ __forceinline__ float f2lo(unsigned long long v) {
    return __uint_as_float((unsigned)v);
}
__device__ __forceinline__ float f2hi(unsigned long long v) {
    return __uint_as_float((unsigned)(v >> 32));
}
__device__ __forceinline__ unsigned long long rep2(float f) {
    unsigned long long r;
    asm("mov.b64 %0, {%1, %1};" : "=l"(r) : "r"(__float_as_uint(f)));
    return r;
}

// ---------------- zero/init (capture-safe) ---------------------------------
__global__ void k_zero(int N, int NG32) {
    int i = blockIdx.x * blockDim.x + threadIdx.x;
    if (i < N) { d_cnt[i] = 0; d_deg[i] = 1.0f; }  // 1.0 = self-loop
    if (i < NG32) d_g[i] = 0.f;
}

// ---------------- CSR build ----------------
// counts + degree in one pass over edges.
__global__ void k_hist(const int* __restrict__ dst,
                       const float* __restrict__ w, int E) {
    int e = blockIdx.x * blockDim.x + threadIdx.x;
    if (e < E) {
        int d = __ldg(dst + e);
        atomicAdd(&d_cnt[d], 1);
        red_add_f32(&d_deg[d], __ldg(w + e));
    }
}

__global__ __launch_bounds__(1024) void k_scanA(int N) {
    __shared__ int sh[1024];
    int i = blockIdx.x * 1024 + threadIdx.x;
    int v = (i < N) ? d_cnt[i] : 0;
    sh[threadIdx.x] = v;
    __syncthreads();
#pragma unroll
    for (int off = 1; off < 1024; off <<= 1) {
        int t = (threadIdx.x >= off) ? sh[threadIdx.x - off] : 0;
        __syncthreads();
        sh[threadIdx.x] += t;
        __syncthreads();
    }
    if (i < N) d_scan[i] = sh[threadIdx.x];
    if (threadIdx.x == 1023) d_bsum[blockIdx.x] = sh[1023];
}

// scanC with in-kernel prefix over block sums.
__global__ __launch_bounds__(1024) void k_scanC(int N) {
    __shared__ int pre;
    if (threadIdx.x < 32) {
        int s = 0;
        for (int t = threadIdx.x; t < (int)blockIdx.x; t += 32) s += d_bsum[t];
#pragma unroll
        for (int off = 16; off; off >>= 1)
            s += __shfl_xor_sync(0xffffffffu, s, off);
        if (threadIdx.x == 0) pre = s;
    }
    __syncthreads();
    int i = blockIdx.x * 1024 + threadIdx.x;
    if (i < N) {
        int incl = d_scan[i] + pre;
        d_rowptr[i + 1] = incl;
        d_cursor[i] = incl - d_cnt[i];
        if (i == 0) d_rowptr[0] = 0;
    }
}

// ---------------- co-kernel: GEMM0 (blocks < GB) || CSR fill (rest) --------
// GEMM0: ms0 = (x @ W0) * dinv, dinv = rsqrt(deg) read from d_deg (hist).
__global__ __launch_bounds__(256) void k_gemm0_fill(
        const float* __restrict__ x, const float* __restrict__ W, int N, int GB,
        const int* __restrict__ src, const int* __restrict__ dst,
        const float* __restrict__ w, int E) {
    __shared__ float XsT[32][132];
    __shared__ float sh_dinv[128];
    int tid = threadIdx.x;

    if ((int)blockIdx.x >= GB) {
        int e = ((int)blockIdx.x - GB) * 256 + tid;
        if (e < E) {
            int d   = __ldg(dst + e);
            int pos = atomicAdd(&d_cursor[d], 1);
            int2 pk;
            pk.x = __ldg(src + e);
            pk.y = __float_as_int(__ldg(w + e));
            d_csr[pos] = pk;
        }
        return;
    }

    int row0 = (int)blockIdx.x * 128;
    int ttx  = tid & 15;
    int tty  = tid >> 4;
    unsigned abase = (unsigned)__cvta_generic_to_shared(XsT) + tty * 32;

    // dinv for this block's 128 rows (coalesced read of hist-built degrees)
    if (tid < 128) {
        int row = row0 + tid;
        float di = 0.f;
        if (row < N) {
            di = rsqrtf(fmaxf(__ldg(d_deg + row), 1e-12f));
            d_dinv[row] = di;
        }
        sh_dinv[tid] = di;
    }

    unsigned long long acc[4][4];
#pragma unroll
    for (int p = 0; p < 4; p++)
#pragma unroll
        for (int c = 0; c < 4; c++) acc[p][c] = 0ull;

    const float4* x4 = (const float4*)x;
    const float4* W4 = (const float4*)W;

    for (int kc = 0; kc < 4; kc++) {
#pragma unroll
        for (int i = 0; i < 4; i++) {
            int v  = tid + 256 * i;
            int rl = v >> 3;
            int c4 = v & 7;
            int row = row0 + rl;
            float4 val = (row < N) ? __ldg(x4 + row * 32 + kc * 8 + c4)
                                   : make_float4(0.f, 0.f, 0.f, 0.f);
            XsT[c4 * 4 + 0][rl] = val.x;
            XsT[c4 * 4 + 1][rl] = val.y;
            XsT[c4 * 4 + 2][rl] = val.z;
            XsT[c4 * 4 + 3][rl] = val.w;
        }
        __syncthreads();

#pragma unroll 4
        for (int k = 0; k < 32; k++) {
            unsigned long long a0, a1, a2, a3;
            unsigned adr = abase + (unsigned)(k * 132 * 4);
            asm("ld.shared.v2.u64 {%0, %1}, [%2];" : "=l"(a0), "=l"(a1) : "r"(adr));
            asm("ld.shared.v2.u64 {%0, %1}, [%2];" : "=l"(a2), "=l"(a3) : "r"(adr + 16));
            float4 b = __ldg(W4 + (kc * 32 + k) * 16 + ttx);
            unsigned long long bx = rep2(b.x), by = rep2(b.y),
                               bz = rep2(b.z), bw = rep2(b.w);
            FMA2(acc[0][0], a0, bx); FMA2(acc[0][1], a0, by);
            FMA2(acc[0][2], a0, bz); FMA2(acc[0][3], a0, bw);
            FMA2(acc[1][0], a1, bx); FMA2(acc[1][1], a1, by);
            FMA2(acc[1][2], a1, bz); FMA2(acc[1][3], a1, bw);
            FMA2(acc[2][0], a2, bx); FMA2(acc[2][1], a2, by);
            FMA2(acc[2][2], a2, bz); FMA2(acc[2][3], a2, bw);
            FMA2(acc[3][0], a3, bx); FMA2(acc[3][1], a3, by);
            FMA2(acc[3][2], a3, bz); FMA2(acc[3][3], a3, bw);
        }
        __syncthreads();
    }

#pragma unroll
    for (int p = 0; p < 4; p++) {
        int r0 = row0 + tty * 8 + 2 * p;
        if (r0 < N) {
            float di = sh_dinv[tty * 8 + 2 * p];
            ((float4*)d_ms0)[r0 * 16 + ttx] =
                make_float4(f2lo(acc[p][0]) * di, f2lo(acc[p][1]) * di,
                            f2lo(acc[p][2]) * di, f2lo(acc[p][3]) * di);
        }
        int r1 = r0 + 1;
        if (r1 < N) {
            float di = sh_dinv[tty * 8 + 2 * p + 1];
            ((float4*)d_ms0)[r1 * 16 + ttx] =
                make_float4(f2hi(acc[p][0]) * di, f2hi(acc[p][1]) * di,
                            f2hi(acc[p][2]) * di, f2hi(acc[p][3]) * di);
        }
    }
}

// ---------------- gather L0: agg0[d] = dinv[d]*(ms0[d] + sum ms0[s]*w) -----
__global__ __launch_bounds__(256) void k_gather0(int N) {
    int gt   = blockIdx.x * blockDim.x + threadIdx.x;
    int node = gt >> 4;
    int lane = gt & 15;
    if (node >= N) return;
    int s0 = __ldg(d_rowptr + node);
    int s1 = __ldg(d_rowptr + node + 1);
    const float4* M = (const float4*)d_ms0;
    float4 acc = __ldg(M + node * 16 + lane);
    int j = s0;
    for (; j + 1 < s1; j += 2) {
        int2 ea = __ldg(d_csr + j);
        int2 eb = __ldg(d_csr + j + 1);
        float wa = __int_as_float(ea.y);
        float wb = __int_as_float(eb.y);
        float4 va = __ldg(M + ea.x * 16 + lane);
        float4 vb = __ldg(M + eb.x * 16 + lane);
        acc.x += va.x * wa + vb.x * wb;
        acc.y += va.y * wa + vb.y * wb;
        acc.z += va.z * wa + vb.z * wb;
        acc.w += va.w * wa + vb.w * wb;
    }
    if (j < s1) {
        int2 ea = __ldg(d_csr + j);
        float wa = __int_as_float(ea.y);
        float4 va = __ldg(M + ea.x * 16 + lane);
        acc.x += va.x * wa; acc.y += va.y * wa;
        acc.z += va.z * wa; acc.w += va.w * wa;
    }
    float dn = __ldg(d_dinv + node);
    acc.x *= dn; acc.y *= dn; acc.z *= dn; acc.w *= dn;
    ((float4*)d_agg0)[node * 16 + lane] = acc;
}

// ---------------- GEMM1: ms1 = (relu(agg0+b0) @ W1) * dinv -----------------
__global__ __launch_bounds__(256) void k_gemm1(const float* __restrict__ b0,
                                               const float* __restrict__ W,
                                               int N) {
    __shared__ float XsT[32][260];
    int tid  = threadIdx.x;
    int row0 = blockIdx.x * 256;
    int ttx  = tid & 7;
    int tty  = tid >> 3;
    unsigned abase = (unsigned)__cvta_generic_to_shared(XsT) + tty * 32;

    unsigned long long acc[4][4];
#pragma unroll
    for (int p = 0; p < 4; p++)
#pragma unroll
        for (int c = 0; c < 4; c++) acc[p][c] = 0ull;

    const float4* A4  = (const float4*)d_agg0;
    const float4* W4  = (const float4*)W;
    const float4* bb4 = (const float4*)b0;

    for (int kc = 0; kc < 2; kc++) {
#pragma unroll
        for (int i = 0; i < 8; i++) {
            int v  = tid + 256 * i;
            int rl = v >> 3;
            int c4 = v & 7;
            int row = row0 + rl;
            float4 val = (row < N) ? A4[row * 16 + kc * 8 + c4]
                                   : make_float4(0.f, 0.f, 0.f, 0.f);
            float4 bv = __ldg(bb4 + kc * 8 + c4);
            XsT[c4 * 4 + 0][rl] = fmaxf(val.x + bv.x, 0.f);
            XsT[c4 * 4 + 1][rl] = fmaxf(val.y + bv.y, 0.f);
            XsT[c4 * 4 + 2][rl] = fmaxf(val.z + bv.z, 0.f);
            XsT[c4 * 4 + 3][rl] = fmaxf(val.w + bv.w, 0.f);
        }
        __syncthreads();

#pragma unroll 4
        for (int k = 0; k < 32; k++) {
            unsigned long long a0, a1, a2, a3;
            unsigned adr = abase + (unsigned)(k * 260 * 4);
            asm("ld.shared.v2.u64 {%0, %1}, [%2];" : "=l"(a0), "=l"(a1) : "r"(adr));
            asm("ld.shared.v2.u64 {%0, %1}, [%2];" : "=l"(a2), "=l"(a3) : "r"(adr + 16));
            float4 b = __ldg(W4 + (kc * 32 + k) * 8 + ttx);
            unsigned long long bx = rep2(b.x), by = rep2(b.y),
                               bz = rep2(b.z), bw = rep2(b.w);
            FMA2(acc[0][0], a0, bx); FMA2(acc[0][1], a0, by);
            FMA2(acc[0][2], a0, bz); FMA2(acc[0][3], a0, bw);
            FMA2(acc[1][0], a1, bx); FMA2(acc[1][1], a1, by);
            FMA2(acc[1][2], a1, bz); FMA2(acc[1][3], a1, bw);
            FMA2(acc[2][0], a2, bx); FMA2(acc[2][1], a2, by);
            FMA2(acc[2][2], a2, bz); FMA2(acc[2][3], a2, bw);
            FMA2(acc[3][0], a3, bx); FMA2(acc[3][1], a3, by);
            FMA2(acc[3][2], a3, bz); FMA2(acc[3][3], a3, bw);
        }
        __syncthreads();
    }

#pragma unroll
    for (int p = 0; p < 4; p++) {
        int r0 = row0 + tty * 8 + 2 * p;
        if (r0 < N) {
            float di = d_dinv[r0];
            ((float4*)d_ms1)[r0 * 8 + ttx] =
                make_float4(f2lo(acc[p][0]) * di, f2lo(acc[p][1]) * di,
                            f2lo(acc[p][2]) * di, f2lo(acc[p][3]) * di);
        }
        int r1 = r0 + 1;
        if (r1 < N) {
            float di = d_dinv[r1];
            ((float4*)d_ms1)[r1 * 8 + ttx] =
                make_float4(f2hi(acc[p][0]) * di, f2hi(acc[p][1]) * di,
                            f2hi(acc[p][2]) * di, f2hi(acc[p][3]) * di);
        }
    }
}

// ---------------- gather L1 + pool (fused) ---------------------------------
__global__ __launch_bounds__(256) void k_gather1_pool(const int* __restrict__ ngi,
                                                      const float* __restrict__ b1,
                                                      int N) {
    int gt   = blockIdx.x * blockDim.x + threadIdx.x;
    int node = gt >> 3;
    int lane = gt & 7;
    int wl   = threadIdx.x & 31;

    float4 acc = make_float4(0.f, 0.f, 0.f, 0.f);
    int gi = -1;
    if (node < N) {
        int s0 = __ldg(d_rowptr + node);
        int s1 = __ldg(d_rowptr + node + 1);
        const float4* M = (const float4*)d_ms1;
        acc = __ldg(M + node * 8 + lane);
        int j = s0;
        for (; j + 1 < s1; j += 2) {
            int2 ea = __ldg(d_csr + j);
            int2 eb = __ldg(d_csr + j + 1);
            float wa = __int_as_float(ea.y);
            float wb = __int_as_float(eb.y);
            float4 va = __ldg(M + ea.x * 8 + lane);
            float4 vb = __ldg(M + eb.x * 8 + lane);
            acc.x += va.x * wa + vb.x * wb;
            acc.y += va.y * wa + vb.y * wb;
            acc.z += va.z * wa + vb.z * wb;
            acc.w += va.w * wa + vb.w * wb;
        }
        if (j < s1) {
            int2 ea = __ldg(d_csr + j);
            float wa = __int_as_float(ea.y);
            float4 va = __ldg(M + ea.x * 8 + lane);
            acc.x += va.x * wa; acc.y += va.y * wa;
            acc.z += va.z * wa; acc.w += va.w * wa;
        }
        float dn = __ldg(d_dinv + node);
        float4 bb = __ldg((const float4*)b1 + lane);
        acc.x = fmaxf(acc.x * dn + bb.x, 0.f);
        acc.y = fmaxf(acc.y * dn + bb.y, 0.f);
        acc.z = fmaxf(acc.z * dn + bb.z, 0.f);
        acc.w = fmaxf(acc.w * dn + bb.w, 0.f);
        gi = __ldg(ngi + node);
    }

    int gi0  = __shfl_sync(0xffffffffu, gi, 0);
    int gi31 = __shfl_sync(0xffffffffu, gi, 31);
    if (gi0 == gi31 && gi0 >= 0) {
        acc.x += __shfl_xor_sync(0xffffffffu, acc.x, 8);
        acc.y += __shfl_xor_sync(0xffffffffu, acc.y, 8);
        acc.z += __shfl_xor_sync(0xffffffffu, acc.z, 8);
        acc.w += __shfl_xor_sync(0xffffffffu, acc.w, 8);
        acc.x += __shfl_xor_sync(0xffffffffu, acc.x, 16);
        acc.y += __shfl_xor_sync(0xffffffffu, acc.y, 16);
        acc.z += __shfl_xor_sync(0xffffffffu, acc.z, 16);
        acc.w += __shfl_xor_sync(0xffffffffu, acc.w, 16);
        if (wl < 8) red_add_v4(d_g + gi0 * 32 + wl * 4, acc);
    } else if (gi >= 0) {
        red_add_v4(d_g + gi * 32 + lane * 4, acc);
    }
}

// ---------------- MLP head -------------------------------------------------
__global__ __launch_bounds__(128) void k_mlp(const float* __restrict__ Wm1,
                                             const float* __restrict__ bm1,
                                             const float* __restrict__ Wm2,
                                             const float* __restrict__ bm2,
                                             float* __restrict__ out) {
    __shared__ float gs[32];
    __shared__ float hs[128];
    int gr = blockIdx.x;
    int t  = threadIdx.x;
    if (t < 32) gs[t] = d_g[gr * 32 + t];
    __syncthreads();
    float acc = __ldg(bm1 + t);
#pragma unroll
    for (int k = 0; k < 32; k++) acc += gs[k] * __ldg(Wm1 + k * 128 + t);
    hs[t] = fmaxf(acc, 0.f);
    __syncthreads();
    if (t < 2) {
        float a = __ldg(bm2 + t);
#pragma unroll 8
        for (int k = 0; k < 128; k++) a += hs[k] * __ldg(Wm2 + k * 2 + t);
        out[gr * 2 + t] = a;
    }
}

// ---------------------------------------------------------------------------
extern "C" void kernel_launch(void* const* d_in, const int* in_sizes, int n_in,
                              void* d_out, int out_size) {
    const float* x   = (const float*)d_in[0];
    const int*   ei  = (const int*)d_in[1];
    const float* ew  = (const float*)d_in[2];
    const int*   ngi = (const int*)d_in[3];
    const float* W0  = (const float*)d_in[4];
    const float* b0  = (const float*)d_in[5];
    const float* W1  = (const float*)d_in[6];
    const float* b1  = (const float*)d_in[7];
    const float* Wm1 = (const float*)d_in[8];
    const float* bm1 = (const float*)d_in[9];
    const float* Wm2 = (const float*)d_in[10];
    const float* bm2 = (const float*)d_in[11];
    float* out = (float*)d_out;

    int N  = in_sizes[0] / 128;
    int E  = in_sizes[2];
    int NG = out_size / 2;
    const int* src = ei;
    const int* dst = ei + E;
    int NB = (N + 1023) / 1024;
    int GB = (N + 127) / 128;           // gemm0 blocks (first)
    int FB = (E + 255) / 256;           // fill blocks  (after)

    int zmax = (N > NG * 32) ? N : NG * 32;
    k_zero <<<(zmax + 255) / 256, 256>>>(N, NG * 32);

    // CSR build prefix (counts+deg, scans)
    k_hist <<<(E + 255) / 256, 256>>>(dst, ew, E);
    k_scanA<<<NB, 1024>>>(N);
    k_scanC<<<NB, 1024>>>(N);

    // co-scheduled: GEMM0 (deg from hist) || CSR fill (cursor from scanC)
    k_gemm0_fill<<<GB + FB, 256>>>(x, W0, N, GB, src, dst, ew, E);

    k_gather0<<<(N * 16 + 255) / 256, 256>>>(N);

    k_gemm1       <<<(N + 255) / 256, 256>>>(b0, W1, N);
    k_gather1_pool<<<(N * 8 + 255) / 256, 256>>>(ngi, b1, N);

    k_mlp<<<NG, 128>>>(Wm1, bm1, Wm2, bm2, out);
}

// round 16
// speedup vs baseline: 1.7698x; 1.0891x over previous
#include <cuda_runtime.h>
#include <cuda_fp16.h>

// ---------------------------------------------------------------------------
// GCN: h0 = relu(Â x W0 + b0); h1 = relu(Â h0 W1 + b1);
//      g = segment_sum(h1, graph); logits = relu(g Wm1 + bm1) Wm2 + bm2
// Â = D^-1/2 (A+I) D^-1/2.
// This round: ms0/ms1 stored fp16 (fp32 accumulation in gathers) -> gather
// L2 traffic halved. Degree from k_hist; gemm0 || CSR fill co-scheduled.
// ---------------------------------------------------------------------------

#define MAXN 100000
#define MAXE 1600000
#define MAXG 1000

__device__ int      d_cnt   [MAXN];
__device__ int      d_scan  [MAXN];
__device__ int      d_bsum  [128];
__device__ int      d_rowptr[MAXN + 1];
__device__ int      d_cursor[MAXN];
__device__ int2     d_csr   [MAXE];      // {src, weight bits} per in-edge
__device__ float    d_deg   [MAXN];      // 1 + sum in-weights (built by k_hist)
__device__ float    d_dinv  [MAXN];
__device__ unsigned d_ms0h  [MAXN * 32]; // (x@W0)*dinv, half2 x32 per row
__device__ float    d_agg0  [MAXN * 64];
__device__ unsigned d_ms1h  [MAXN * 16]; // (h0@W1)*dinv, half2 x16 per row
__device__ float    d_g     [MAXG * 32];

__device__ __forceinline__ void red_add_v4(float* addr, float4 v) {
    asm volatile("red.global.add.v4.f32 [%0], {%1, %2, %3, %4};"
                 :: "l"(addr), "f"(v.x), "f"(v.y), "f"(v.z), "f"(v.w)
                 : "memory");
}

__device__ __forceinline__ void red_add_f32(float* addr, float v) {
    asm volatile("red.global.add.f32 [%0], %1;" :: "l"(addr), "f"(v) : "memory");
}

#define FMA2(d, a, b) \
    asm("fma.rn.f32x2 %0, %1, %2, %0;" : "+l"(d) : "l"(a), "l"(b))

__device__ __forceinline__ float f2lo(unsigned long long v) {
    return __uint_as_float((unsigned)v);
}
__device__ __forceinline__ float f2hi(unsigned long long v) {
    return __uint_as_float((unsigned)(v >> 32));
}
__device__ __forceinline__ unsigned long long rep2(float f) {
    unsigned long long r;
    asm("mov.b64 %0, {%1, %1};" : "=l"(r) : "r"(__float_as_uint(f)));
    return r;
}

__device__ __forceinline__ unsigned packh2(float a, float b) {
    __half2 h = __floats2half2_rn(a, b);
    return *(unsigned*)&h;
}
// unpack uint2 (4 halves) -> 4 floats
__device__ __forceinline__ float4 unpackh4(uint2 u) {
    __half2 h01 = *(__half2*)&u.x;
    __half2 h23 = *(__half2*)&u.y;
    float2 f01 = __half22float2(h01);
    float2 f23 = __half22float2(h23);
    return make_float4(f01.x, f01.y, f23.x, f23.y);
}

// ---------------- zero/init (capture-safe) ---------------------------------
__global__ void k_zero(int N, int NG32) {
    int i = blockIdx.x * blockDim.x + threadIdx.x;
    if (i < N) { d_cnt[i] = 0; d_deg[i] = 1.0f; }  // 1.0 = self-loop
    if (i < NG32) d_g[i] = 0.f;
}

// ---------------- CSR build: counts + degree in one edge pass --------------
__global__ void k_hist(const int* __restrict__ dst,
                       const float* __restrict__ w, int E) {
    int e = blockIdx.x * blockDim.x + threadIdx.x;
    if (e < E) {
        int d = __ldg(dst + e);
        atomicAdd(&d_cnt[d], 1);
        red_add_f32(&d_deg[d], __ldg(w + e));
    }
}

__global__ __launch_bounds__(1024) void k_scanA(int N) {
    __shared__ int sh[1024];
    int i = blockIdx.x * 1024 + threadIdx.x;
    int v = (i < N) ? d_cnt[i] : 0;
    sh[threadIdx.x] = v;
    __syncthreads();
#pragma unroll
    for (int off = 1; off < 1024; off <<= 1) {
        int t = (threadIdx.x >= off) ? sh[threadIdx.x - off] : 0;
        __syncthreads();
        sh[threadIdx.x] += t;
        __syncthreads();
    }
    if (i < N) d_scan[i] = sh[threadIdx.x];
    if (threadIdx.x == 1023) d_bsum[blockIdx.x] = sh[1023];
}

__global__ __launch_bounds__(1024) void k_scanC(int N) {
    __shared__ int pre;
    if (threadIdx.x < 32) {
        int s = 0;
        for (int t = threadIdx.x; t < (int)blockIdx.x; t += 32) s += d_bsum[t];
#pragma unroll
        for (int off = 16; off; off >>= 1)
            s += __shfl_xor_sync(0xffffffffu, s, off);
        if (threadIdx.x == 0) pre = s;
    }
    __syncthreads();
    int i = blockIdx.x * 1024 + threadIdx.x;
    if (i < N) {
        int incl = d_scan[i] + pre;
        d_rowptr[i + 1] = incl;
        d_cursor[i] = incl - d_cnt[i];
        if (i == 0) d_rowptr[0] = 0;
    }
}

// ---------------- co-kernel: GEMM0 (blocks < GB) || CSR fill (rest) --------
__global__ __launch_bounds__(256) void k_gemm0_fill(
        const float* __restrict__ x, const float* __restrict__ W, int N, int GB,
        const int* __restrict__ src, const int* __restrict__ dst,
        const float* __restrict__ w, int E) {
    __shared__ float XsT[32][132];
    __shared__ float sh_dinv[128];
    int tid = threadIdx.x;

    if ((int)blockIdx.x >= GB) {
        int e = ((int)blockIdx.x - GB) * 256 + tid;
        if (e < E) {
            int d   = __ldg(dst + e);
            int pos = atomicAdd(&d_cursor[d], 1);
            int2 pk;
            pk.x = __ldg(src + e);
            pk.y = __float_as_int(__ldg(w + e));
            d_csr[pos] = pk;
        }
        return;
    }

    int row0 = (int)blockIdx.x * 128;
    int ttx  = tid & 15;
    int tty  = tid >> 4;
    unsigned abase = (unsigned)__cvta_generic_to_shared(XsT) + tty * 32;

    if (tid < 128) {
        int row = row0 + tid;
        float di = 0.f;
        if (row < N) {
            di = rsqrtf(fmaxf(__ldg(d_deg + row), 1e-12f));
            d_dinv[row] = di;
        }
        sh_dinv[tid] = di;
    }

    unsigned long long acc[4][4];
#pragma unroll
    for (int p = 0; p < 4; p++)
#pragma unroll
        for (int c = 0; c < 4; c++) acc[p][c] = 0ull;

    const float4* x4 = (const float4*)x;
    const float4* W4 = (const float4*)W;

    for (int kc = 0; kc < 4; kc++) {
#pragma unroll
        for (int i = 0; i < 4; i++) {
            int v  = tid + 256 * i;
            int rl = v >> 3;
            int c4 = v & 7;
            int row = row0 + rl;
            float4 val = (row < N) ? __ldg(x4 + row * 32 + kc * 8 + c4)
                                   : make_float4(0.f, 0.f, 0.f, 0.f);
            XsT[c4 * 4 + 0][rl] = val.x;
            XsT[c4 * 4 + 1][rl] = val.y;
            XsT[c4 * 4 + 2][rl] = val.z;
            XsT[c4 * 4 + 3][rl] = val.w;
        }
        __syncthreads();

#pragma unroll 4
        for (int k = 0; k < 32; k++) {
            unsigned long long a0, a1, a2, a3;
            unsigned adr = abase + (unsigned)(k * 132 * 4);
            asm("ld.shared.v2.u64 {%0, %1}, [%2];" : "=l"(a0), "=l"(a1) : "r"(adr));
            asm("ld.shared.v2.u64 {%0, %1}, [%2];" : "=l"(a2), "=l"(a3) : "r"(adr + 16));
            float4 b = __ldg(W4 + (kc * 32 + k) * 16 + ttx);
            unsigned long long bx = rep2(b.x), by = rep2(b.y),
                               bz = rep2(b.z), bw = rep2(b.w);
            FMA2(acc[0][0], a0, bx); FMA2(acc[0][1], a0, by);
            FMA2(acc[0][2], a0, bz); FMA2(acc[0][3], a0, bw);
            FMA2(acc[1][0], a1, bx); FMA2(acc[1][1], a1, by);
            FMA2(acc[1][2], a1, bz); FMA2(acc[1][3], a1, bw);
            FMA2(acc[2][0], a2, bx); FMA2(acc[2][1], a2, by);
            FMA2(acc[2][2], a2, bz); FMA2(acc[2][3], a2, bw);
            FMA2(acc[3][0], a3, bx); FMA2(acc[3][1], a3, by);
            FMA2(acc[3][2], a3, bz); FMA2(acc[3][3], a3, bw);
        }
        __syncthreads();
    }

#pragma unroll
    for (int p = 0; p < 4; p++) {
        int r0 = row0 + tty * 8 + 2 * p;
        if (r0 < N) {
            float di = sh_dinv[tty * 8 + 2 * p];
            uint2 u;
            u.x = packh2(f2lo(acc[p][0]) * di, f2lo(acc[p][1]) * di);
            u.y = packh2(f2lo(acc[p][2]) * di, f2lo(acc[p][3]) * di);
            ((uint2*)d_ms0h)[r0 * 16 + ttx] = u;
        }
        int r1 = r0 + 1;
        if (r1 < N) {
            float di = sh_dinv[tty * 8 + 2 * p + 1];
            uint2 u;
            u.x = packh2(f2hi(acc[p][0]) * di, f2hi(acc[p][1]) * di);
            u.y = packh2(f2hi(acc[p][2]) * di, f2hi(acc[p][3]) * di);
            ((uint2*)d_ms0h)[r1 * 16 + ttx] = u;
        }
    }
}

// ---------------- gather L0: agg0[d] = dinv[d]*(ms0[d] + sum ms0[s]*w) -----
// 16 lanes per node; lane covers 4 cols = one uint2 (4 halves), fp32 accum.
__global__ __launch_bounds__(256) void k_gather0(int N) {
    int gt   = blockIdx.x * blockDim.x + threadIdx.x;
    int node = gt >> 4;
    int lane = gt & 15;
    if (node >= N) return;
    int s0 = __ldg(d_rowptr + node);
    int s1 = __ldg(d_rowptr + node + 1);
    const uint2* M = (const uint2*)d_ms0h;
    float4 acc = unpackh4(__ldg(M + node * 16 + lane));   // self term
    int j = s0;
    for (; j + 1 < s1; j += 2) {
        int2 ea = __ldg(d_csr + j);
        int2 eb = __ldg(d_csr + j + 1);
        float wa = __int_as_float(ea.y);
        float wb = __int_as_float(eb.y);
        float4 va = unpackh4(__ldg(M + ea.x * 16 + lane));
        float4 vb = unpackh4(__ldg(M + eb.x * 16 + lane));
        acc.x += va.x * wa + vb.x * wb;
        acc.y += va.y * wa + vb.y * wb;
        acc.z += va.z * wa + vb.z * wb;
        acc.w += va.w * wa + vb.w * wb;
    }
    if (j < s1) {
        int2 ea = __ldg(d_csr + j);
        float wa = __int_as_float(ea.y);
        float4 va = unpackh4(__ldg(M + ea.x * 16 + lane));
        acc.x += va.x * wa; acc.y += va.y * wa;
        acc.z += va.z * wa; acc.w += va.w * wa;
    }
    float dn = __ldg(d_dinv + node);
    acc.x *= dn; acc.y *= dn; acc.z *= dn; acc.w *= dn;
    ((float4*)d_agg0)[node * 16 + lane] = acc;
}

// ---------------- GEMM1: ms1 = (relu(agg0+b0) @ W1) * dinv -----------------
__global__ __launch_bounds__(256) void k_gemm1(const float* __restrict__ b0,
                                               const float* __restrict__ W,
                                               int N) {
    __shared__ float XsT[32][260];
    int tid  = threadIdx.x;
    int row0 = blockIdx.x * 256;
    int ttx  = tid & 7;
    int tty  = tid >> 3;
    unsigned abase = (unsigned)__cvta_generic_to_shared(XsT) + tty * 32;

    unsigned long long acc[4][4];
#pragma unroll
    for (int p = 0; p < 4; p++)
#pragma unroll
        for (int c = 0; c < 4; c++) acc[p][c] = 0ull;

    const float4* A4  = (const float4*)d_agg0;
    const float4* W4  = (const float4*)W;
    const float4* bb4 = (const float4*)b0;

    for (int kc = 0; kc < 2; kc++) {
#pragma unroll
        for (int i = 0; i < 8; i++) {
            int v  = tid + 256 * i;
            int rl = v >> 3;
            int c4 = v & 7;
            int row = row0 + rl;
            float4 val = (row < N) ? A4[row * 16 + kc * 8 + c4]
                                   : make_float4(0.f, 0.f, 0.f, 0.f);
            float4 bv = __ldg(bb4 + kc * 8 + c4);
            XsT[c4 * 4 + 0][rl] = fmaxf(val.x + bv.x, 0.f);
            XsT[c4 * 4 + 1][rl] = fmaxf(val.y + bv.y, 0.f);
            XsT[c4 * 4 + 2][rl] = fmaxf(val.z + bv.z, 0.f);
            XsT[c4 * 4 + 3][rl] = fmaxf(val.w + bv.w, 0.f);
        }
        __syncthreads();

#pragma unroll 4
        for (int k = 0; k < 32; k++) {
            unsigned long long a0, a1, a2, a3;
            unsigned adr = abase + (unsigned)(k * 260 * 4);
            asm("ld.shared.v2.u64 {%0, %1}, [%2];" : "=l"(a0), "=l"(a1) : "r"(adr));
            asm("ld.shared.v2.u64 {%0, %1}, [%2];" : "=l"(a2), "=l"(a3) : "r"(adr + 16));
            float4 b = __ldg(W4 + (kc * 32 + k) * 8 + ttx);
            unsigned long long bx = rep2(b.x), by = rep2(b.y),
                               bz = rep2(b.z), bw = rep2(b.w);
            FMA2(acc[0][0], a0, bx); FMA2(acc[0][1], a0, by);
            FMA2(acc[0][2], a0, bz); FMA2(acc[0][3], a0, bw);
            FMA2(acc[1][0], a1, bx); FMA2(acc[1][1], a1, by);
            FMA2(acc[1][2], a1, bz); FMA2(acc[1][3], a1, bw);
            FMA2(acc[2][0], a2, bx); FMA2(acc[2][1], a2, by);
            FMA2(acc[2][2], a2, bz); FMA2(acc[2][3], a2, bw);
            FMA2(acc[3][0], a3, bx); FMA2(acc[3][1], a3, by);
            FMA2(acc[3][2], a3, bz); FMA2(acc[3][3], a3, bw);
        }
        __syncthreads();
    }

#pragma unroll
    for (int p = 0; p < 4; p++) {
        int r0 = row0 + tty * 8 + 2 * p;
        if (r0 < N) {
            float di = d_dinv[r0];
            uint2 u;
            u.x = packh2(f2lo(acc[p][0]) * di, f2lo(acc[p][1]) * di);
            u.y = packh2(f2lo(acc[p][2]) * di, f2lo(acc[p][3]) * di);
            ((uint2*)d_ms1h)[r0 * 8 + ttx] = u;
        }
        int r1 = r0 + 1;
        if (r1 < N) {
            float di = d_dinv[r1];
            uint2 u;
            u.x = packh2(f2hi(acc[p][0]) * di, f2hi(acc[p][1]) * di);
            u.y = packh2(f2hi(acc[p][2]) * di, f2hi(acc[p][3]) * di);
            ((uint2*)d_ms1h)[r1 * 8 + ttx] = u;
        }
    }
}

// ---------------- gather L1 + pool (fused) ---------------------------------
__global__ __launch_bounds__(256) void k_gather1_pool(const int* __restrict__ ngi,
                                                      const float* __restrict__ b1,
                                                      int N) {
    int gt   = blockIdx.x * blockDim.x + threadIdx.x;
    int node = gt >> 3;
    int lane = gt & 7;
    int wl   = threadIdx.x & 31;

    float4 acc = make_float4(0.f, 0.f, 0.f, 0.f);
    int gi = -1;
    if (node < N) {
        int s0 = __ldg(d_rowptr + node);
        int s1 = __ldg(d_rowptr + node + 1);
        const uint2* M = (const uint2*)d_ms1h;
        acc = unpackh4(__ldg(M + node * 8 + lane));
        int j = s0;
        for (; j + 1 < s1; j += 2) {
            int2 ea = __ldg(d_csr + j);
            int2 eb = __ldg(d_csr + j + 1);
            float wa = __int_as_float(ea.y);
            float wb = __int_as_float(eb.y);
            float4 va = unpackh4(__ldg(M + ea.x * 8 + lane));
            float4 vb = unpackh4(__ldg(M + eb.x * 8 + lane));
            acc.x += va.x * wa + vb.x * wb;
            acc.y += va.y * wa + vb.y * wb;
            acc.z += va.z * wa + vb.z * wb;
            acc.w += va.w * wa + vb.w * wb;
        }
        if (j < s1) {
            int2 ea = __ldg(d_csr + j);
            float wa = __int_as_float(ea.y);
            float4 va = unpackh4(__ldg(M + ea.x * 8 + lane));
            acc.x += va.x * wa; acc.y += va.y * wa;
            acc.z += va.z * wa; acc.w += va.w * wa;
        }
        float dn = __ldg(d_dinv + node);
        float4 bb = __ldg((const float4*)b1 + lane);
        acc.x = fmaxf(acc.x * dn + bb.x, 0.f);
        acc.y = fmaxf(acc.y * dn + bb.y, 0.f);
        acc.z = fmaxf(acc.z * dn + bb.z, 0.f);
        acc.w = fmaxf(acc.w * dn + bb.w, 0.f);
        gi = __ldg(ngi + node);
    }

    int gi0  = __shfl_sync(0xffffffffu, gi, 0);
    int gi31 = __shfl_sync(0xffffffffu, gi, 31);
    if (gi0 == gi31 && gi0 >= 0) {
        acc.x += __shfl_xor_sync(0xffffffffu, acc.x, 8);
        acc.y += __shfl_xor_sync(0xffffffffu, acc.y, 8);
        acc.z += __shfl_xor_sync(0xffffffffu, acc.z, 8);
        acc.w += __shfl_xor_sync(0xffffffffu, acc.w, 8);
        acc.x += __shfl_xor_sync(0xffffffffu, acc.x, 16);
        acc.y += __shfl_xor_sync(0xffffffffu, acc.y, 16);
        acc.z += __shfl_xor_sync(0xffffffffu, acc.z, 16);
        acc.w += __shfl_xor_sync(0xffffffffu, acc.w, 16);
        if (wl < 8) red_add_v4(d_g + gi0 * 32 + wl * 4, acc);
    } else if (gi >= 0) {
        red_add_v4(d_g + gi * 32 + lane * 4, acc);
    }
}

// ---------------- MLP head -------------------------------------------------
__global__ __launch_bounds__(128) void k_mlp(const float* __restrict__ Wm1,
                                             const float* __restrict__ bm1,
                                             const float* __restrict__ Wm2,
                                             const float* __restrict__ bm2,
                                             float* __restrict__ out) {
    __shared__ float gs[32];
    __shared__ float hs[128];
    int gr = blockIdx.x;
    int t  = threadIdx.x;
    if (t < 32) gs[t] = d_g[gr * 32 + t];
    __syncthreads();
    float acc = __ldg(bm1 + t);
#pragma unroll
    for (int k = 0; k < 32; k++) acc += gs[k] * __ldg(Wm1 + k * 128 + t);
    hs[t] = fmaxf(acc, 0.f);
    __syncthreads();
    if (t < 2) {
        float a = __ldg(bm2 + t);
#pragma unroll 8
        for (int k = 0; k < 128; k++) a += hs[k] * __ldg(Wm2 + k * 2 + t);
        out[gr * 2 + t] = a;
    }
}

// ---------------------------------------------------------------------------
extern "C" void kernel_launch(void* const* d_in, const int* in_sizes, int n_in,
                              void* d_out, int out_size) {
    const float* x   = (const float*)d_in[0];
    const int*   ei  = (const int*)d_in[1];
    const float* ew  = (const float*)d_in[2];
    const int*   ngi = (const int*)d_in[3];
    const float* W0  = (const float*)d_in[4];
    const float* b0  = (const float*)d_in[5];
    const float* W1  = (const float*)d_in[6];
    const float* b1  = (const float*)d_in[7];
    const float* Wm1 = (const float*)d_in[8];
    const float* bm1 = (const float*)d_in[9];
    const float* Wm2 = (const float*)d_in[10];
    const float* bm2 = (const float*)d_in[11];
    float* out = (float*)d_out;

    int N  = in_sizes[0] / 128;
    int E  = in_sizes[2];
    int NG = out_size / 2;
    const int* src = ei;
    const int* dst = ei + E;
    int NB = (N + 1023) / 1024;
    int GB = (N + 127) / 128;           // gemm0 blocks (first)
    int FB = (E + 255) / 256;           // fill blocks  (after)

    int zmax = (N > NG * 32) ? N : NG * 32;
    k_zero <<<(zmax + 255) / 256, 256>>>(N, NG * 32);

    k_hist <<<(E + 255) / 256, 256>>>(dst, ew, E);
    k_scanA<<<NB, 1024>>>(N);
    k_scanC<<<NB, 1024>>>(N);

    k_gemm0_fill<<<GB + FB, 256>>>(x, W0, N, GB, src, dst, ew, E);

    k_gather0<<<(N * 16 + 255) / 256, 256>>>(N);

    k_gemm1       <<<(N + 255) / 256, 256>>>(b0, W1, N);
    k_gather1_pool<<<(N * 8 + 255) / 256, 256>>>(ngi, b1, N);

    k_mlp<<<NG, 128>>>(Wm1, bm1, Wm2, bm2, out);
}